// round 10
// baseline (speedup 1.0000x reference)
#include <cuda_runtime.h>
#include <cuda_bf16.h>
#include <cstdint>

// ---------------------------------------------------------------------------
// GCNWithSubgraphs: gather-based, cp.async tf32 MMA GEMMs (dinv-prescaled
// fp32 output), pure-sum gathers. Stream-forked graph. Glob gather is
// edge-split (4 warps/node) with fused final FC (last-block pattern).
// ---------------------------------------------------------------------------

#define H 256
#define MAX_NSUB  32768
#define MAX_NGLOB 65536
#define MAX_S     1024
#define MAX_ESUB  262144
#define MAX_EGLOB 1048576

__device__ float g_h_sub[MAX_NSUB * H];
__device__ float g_h_glob[MAX_NGLOB * H];
__device__ float g_pooledW[MAX_S * H];
__device__ float g_pool_sum[MAX_S * H];
__device__ float g_pool_cnt[MAX_S];
__device__ float g_gemb[H];
__device__ int   g_done;

__device__ int   g_cnt_sub[MAX_NSUB];
__device__ int   g_off_sub[MAX_NSUB + 1];
__device__ int   g_cur_sub[MAX_NSUB];
__device__ float g_dinv_sub[MAX_NSUB];
__device__ int   g_srcs_sub[MAX_ESUB];

__device__ int   g_cnt_glob[MAX_NGLOB];
__device__ int   g_off_glob[MAX_NGLOB + 1];
__device__ int   g_cur_glob[MAX_NGLOB];
__device__ float g_dinv_glob[MAX_NGLOB];
__device__ int   g_srcs_glob[MAX_EGLOB];

__device__ int   g_bsum_sub[256];
__device__ int   g_bsum_glob[256];

__device__ __forceinline__ void red_add_v4(float* a, float v0, float v1, float v2, float v3) {
    asm volatile("red.global.add.v4.f32 [%0], {%1,%2,%3,%4};"
                 :: "l"(a), "f"(v0), "f"(v1), "f"(v2), "f"(v3)
                 : "memory");
}

__device__ __forceinline__ void cp_async16(void* smem_dst, const void* gmem_src) {
    uint32_t s = (uint32_t)__cvta_generic_to_shared(smem_dst);
    asm volatile("cp.async.cg.shared.global [%0], [%1], 16;" :: "r"(s), "l"(gmem_src));
}
__device__ __forceinline__ void cp_commit() {
    asm volatile("cp.async.commit_group;" ::: "memory");
}
template <int N>
__device__ __forceinline__ void cp_wait() {
    asm volatile("cp.async.wait_group %0;" :: "n"(N) : "memory");
}

// ---------------------------------------------------------------------------
__global__ void k_init(int n_sub, int n_glob, int s) {
    int i = blockIdx.x * blockDim.x + threadIdx.x;
    if (i < n_sub)  g_cnt_sub[i]  = 0;
    if (i < n_glob) g_cnt_glob[i] = 0;
    if (i < s * H)  g_pool_sum[i] = 0.0f;
    if (i < s)      g_pool_cnt[i] = 0.0f;
    if (i < H)      g_gemb[i]     = 0.0f;
    if (i == 0)     g_done        = 0;
}

__global__ void k_count_all(const int* __restrict__ cols_sub, int E_sub,
                            const int* __restrict__ cols_glob, int E_glob,
                            const int* __restrict__ batch, int n_sub) {
    int i = blockIdx.x * blockDim.x + threadIdx.x;
    if (i < E_glob) atomicAdd(&g_cnt_glob[cols_glob[i]], 1);
    if (i < E_sub)  atomicAdd(&g_cnt_sub[cols_sub[i]], 1);
    if (i < n_sub)  atomicAdd(&g_pool_cnt[batch[i]], 1.0f);
}

__global__ void k_dinv(int n_sub, int n_glob) {
    int i = blockIdx.x * blockDim.x + threadIdx.x;
    if (i < n_sub)  g_dinv_sub[i]  = rsqrtf((float)(g_cnt_sub[i] + 1));
    if (i < n_glob) g_dinv_glob[i] = rsqrtf((float)(g_cnt_glob[i] + 1));
}

// ---------------------------------------------------------------------------
// tf32 MMA GEMM: C[M,256](f32) = (A[M,256] @ B[256,256]) * rowscale
// cp.async double-buffered, no STS, no cvt. 128x128 block, 256 thr, BK=32.
// ---------------------------------------------------------------------------
#define ASP 36
#define BSP 136
#define ASZ (128 * ASP)
#define BSZ (32 * BSP)
#define STG (ASZ + BSZ)
#define MMA_SMEM (2 * STG * 4)

__global__ __launch_bounds__(256) void k_mma(const float* __restrict__ A,
                                             const float* __restrict__ B,
                                             float* __restrict__ C,
                                             const float* __restrict__ rowscale, int M) {
    extern __shared__ float sm[];

    const int tid  = threadIdx.x;
    const int lane = tid & 31;
    const int wid  = tid >> 5;
    const int warpM = wid >> 1;
    const int warpN = wid & 1;
    const int g  = lane >> 2;
    const int tg = lane & 3;
    const int mb = warpM * 32;
    const int nb = warpN * 64;

    const int bc = blockIdx.x;
    const int br = blockIdx.y;

    const float* Ab = A + (size_t)br * 128 * H;
    const float* Bb = B + bc * 128;

    float c[2][8][4];
    #pragma unroll
    for (int mt = 0; mt < 2; mt++)
        #pragma unroll
        for (int nt = 0; nt < 8; nt++)
            #pragma unroll
            for (int i = 0; i < 4; i++) c[mt][nt][i] = 0.0f;

    auto load_tiles = [&](int stage, int k0) {
        float* as = sm + stage * STG;
        float* bs = as + ASZ;
        #pragma unroll
        for (int p = 0; p < 4; p++) {
            int idx = tid + p * 256;
            int row = idx >> 3;
            int c4  = (idx & 7) * 4;
            cp_async16(&as[row * ASP + c4], Ab + (size_t)row * H + k0 + c4);
        }
        #pragma unroll
        for (int p = 0; p < 4; p++) {
            int idx = tid + p * 256;
            int row = idx >> 5;
            int c4  = (idx & 31) * 4;
            cp_async16(&bs[row * BSP + c4], Bb + (size_t)(k0 + row) * H + c4);
        }
        cp_commit();
    };

    load_tiles(0, 0);

    const int NIT = H / 32;
    for (int it = 0; it < NIT; it++) {
        if (it + 1 < NIT) {
            load_tiles((it + 1) & 1, (it + 1) * 32);
            cp_wait<1>();
        } else {
            cp_wait<0>();
        }
        __syncthreads();

        const uint32_t* as = (const uint32_t*)(sm + (it & 1) * STG);
        const uint32_t* bs = as + ASZ;

        #pragma unroll
        for (int kk = 0; kk < 4; kk++) {
            const int k = kk * 8;
            uint32_t a[2][4];
            #pragma unroll
            for (int mt = 0; mt < 2; mt++) {
                int m = mb + mt * 16 + g;
                a[mt][0] = as[(size_t)m * ASP + k + tg];
                a[mt][1] = as[(size_t)(m + 8) * ASP + k + tg];
                a[mt][2] = as[(size_t)m * ASP + k + tg + 4];
                a[mt][3] = as[(size_t)(m + 8) * ASP + k + tg + 4];
            }
            #pragma unroll
            for (int nt = 0; nt < 8; nt++) {
                int n = nb + nt * 8 + g;
                uint32_t b0 = bs[(size_t)(k + tg) * BSP + n];
                uint32_t b1 = bs[(size_t)(k + tg + 4) * BSP + n];
                #pragma unroll
                for (int mt = 0; mt < 2; mt++) {
                    asm volatile(
                        "mma.sync.aligned.m16n8k8.row.col.f32.tf32.tf32.f32 "
                        "{%0,%1,%2,%3}, {%4,%5,%6,%7}, {%8,%9}, {%0,%1,%2,%3};"
                        : "+f"(c[mt][nt][0]), "+f"(c[mt][nt][1]),
                          "+f"(c[mt][nt][2]), "+f"(c[mt][nt][3])
                        : "r"(a[mt][0]), "r"(a[mt][1]), "r"(a[mt][2]), "r"(a[mt][3]),
                          "r"(b0), "r"(b1));
                }
            }
        }
        __syncthreads();
    }

    float* Cb = C + (size_t)br * 128 * H + bc * 128;
    #pragma unroll
    for (int mt = 0; mt < 2; mt++) {
        int r0 = mb + mt * 16 + g;
        float s0 = 1.0f, s1 = 1.0f;
        if (rowscale) {
            s0 = __ldg(&rowscale[br * 128 + r0]);
            s1 = __ldg(&rowscale[br * 128 + r0 + 8]);
        }
        #pragma unroll
        for (int nt = 0; nt < 8; nt++) {
            int col = nb + nt * 8 + 2 * tg;
            *(float2*)(Cb + (size_t)r0 * H + col)       = make_float2(c[mt][nt][0] * s0, c[mt][nt][1] * s0);
            *(float2*)(Cb + (size_t)(r0 + 8) * H + col) = make_float2(c[mt][nt][2] * s1, c[mt][nt][3] * s1);
        }
    }
}

// ---------------------------------------------------------------------------
// counting sort (both graphs batched)
// ---------------------------------------------------------------------------
__global__ void k_blocksum_all(int NB_sub) {
    __shared__ int sh[256];
    int t = threadIdx.x;
    bool is_sub = (blockIdx.x < NB_sub);
    const int* cnt = is_sub ? g_cnt_sub : g_cnt_glob;
    int cb = is_sub ? blockIdx.x : blockIdx.x - NB_sub;
    sh[t] = cnt[cb * 256 + t];
    __syncthreads();
    #pragma unroll
    for (int s = 128; s > 0; s >>= 1) {
        if (t < s) sh[t] += sh[t + s];
        __syncthreads();
    }
    if (t == 0) (is_sub ? g_bsum_sub : g_bsum_glob)[cb] = sh[0];
}

__global__ void k_scan_bsum_all(int NB_sub, int NB_glob) {
    __shared__ int sh[256];
    int t = threadIdx.x;
    int* bsum = (blockIdx.x == 0) ? g_bsum_sub : g_bsum_glob;
    int NB = (blockIdx.x == 0) ? NB_sub : NB_glob;
    sh[t] = (t < NB) ? bsum[t] : 0;
    __syncthreads();
    #pragma unroll
    for (int d = 1; d < 256; d <<= 1) {
        int v = (t >= d) ? sh[t - d] : 0;
        __syncthreads();
        sh[t] += v;
        __syncthreads();
    }
    int ex = (t == 0) ? 0 : sh[t - 1];
    if (t < NB) bsum[t] = ex;
}

__global__ void k_scan_chunks_all(int NB_sub, int n_sub, int n_glob) {
    __shared__ int sh[256];
    int t = threadIdx.x;
    bool is_sub = (blockIdx.x < NB_sub);
    const int* cnt = is_sub ? g_cnt_sub : g_cnt_glob;
    const int* bsum = is_sub ? g_bsum_sub : g_bsum_glob;
    int* off = is_sub ? g_off_sub : g_off_glob;
    int* cur = is_sub ? g_cur_sub : g_cur_glob;
    int N = is_sub ? n_sub : n_glob;
    int cb = is_sub ? blockIdx.x : blockIdx.x - NB_sub;
    int i = cb * 256 + t;
    int c = cnt[i];
    sh[t] = c;
    __syncthreads();
    #pragma unroll
    for (int d = 1; d < 256; d <<= 1) {
        int v = (t >= d) ? sh[t - d] : 0;
        __syncthreads();
        sh[t] += v;
        __syncthreads();
    }
    int excl = sh[t] - c + bsum[cb];
    off[i] = excl;
    cur[i] = excl;
    if (i == N - 1) off[N] = excl + c;
}

__global__ void k_bucket_all(const int* __restrict__ rows_sub,
                             const int* __restrict__ cols_sub, int E_sub,
                             const int* __restrict__ rows_glob,
                             const int* __restrict__ cols_glob, int E_glob) {
    int i = blockIdx.x * blockDim.x + threadIdx.x;
    if (i < E_sub) {
        int c = cols_sub[i];
        int p = atomicAdd(&g_cur_sub[c], 1);
        g_srcs_sub[p] = rows_sub[i];
    }
    int e = i - E_sub;
    if (e >= 0 && e < E_glob) {
        int c = cols_glob[e];
        int p = atomicAdd(&g_cur_glob[c], 1);
        g_srcs_glob[p] = rows_glob[e];
    }
}

// ---------------------------------------------------------------------------
// sub gather: warp per node; lane owns float4 {lane, lane+32}; 4-edge batch.
// ---------------------------------------------------------------------------
__device__ __forceinline__ void f4_add2(float4 v0, float4 v1, float* acc) {
    acc[0] += v0.x; acc[1] += v0.y; acc[2] += v0.z; acc[3] += v0.w;
    acc[4] += v1.x; acc[5] += v1.y; acc[6] += v1.z; acc[7] += v1.w;
}

__global__ __launch_bounds__(256) void k_gather_sub(const float4* __restrict__ h,
                                                    const float* __restrict__ bias,
                                                    const int* __restrict__ batch, int N) {
    int warp = (blockIdx.x * blockDim.x + threadIdx.x) >> 5;
    int lane = threadIdx.x & 31;
    if (warp >= N) return;

    int base = g_off_sub[warp];
    int end  = g_off_sub[warp + 1];
    const int* srcs = g_srcs_sub;

    float acc[8];
    {
        float4 s0 = __ldg(h + (size_t)warp * 64 + lane);
        float4 s1 = __ldg(h + (size_t)warp * 64 + lane + 32);
        acc[0] = s0.x; acc[1] = s0.y; acc[2] = s0.z; acc[3] = s0.w;
        acc[4] = s1.x; acc[5] = s1.y; acc[6] = s1.z; acc[7] = s1.w;
    }
    int e = base;
    for (; e + 4 <= end; e += 4) {
        int r0 = __ldg(&srcs[e + 0]);
        int r1 = __ldg(&srcs[e + 1]);
        int r2 = __ldg(&srcs[e + 2]);
        int r3 = __ldg(&srcs[e + 3]);
        float4 a0 = __ldg(h + (size_t)r0 * 64 + lane);
        float4 b0 = __ldg(h + (size_t)r0 * 64 + lane + 32);
        float4 a1 = __ldg(h + (size_t)r1 * 64 + lane);
        float4 b1 = __ldg(h + (size_t)r1 * 64 + lane + 32);
        float4 a2 = __ldg(h + (size_t)r2 * 64 + lane);
        float4 b2 = __ldg(h + (size_t)r2 * 64 + lane + 32);
        float4 a3 = __ldg(h + (size_t)r3 * 64 + lane);
        float4 b3 = __ldg(h + (size_t)r3 * 64 + lane + 32);
        f4_add2(a0, b0, acc);
        f4_add2(a1, b1, acc);
        f4_add2(a2, b2, acc);
        f4_add2(a3, b3, acc);
    }
    for (; e < end; e++) {
        int r = __ldg(&srcs[e]);
        float4 a = __ldg(h + (size_t)r * 64 + lane);
        float4 b = __ldg(h + (size_t)r * 64 + lane + 32);
        f4_add2(a, b, acc);
    }

    float di = g_dinv_sub[warp];
    int s = batch[warp];
    float ic = 1.0f / fmaxf(g_pool_cnt[s], 1.0f);
    const float* bp = bias + 4 * lane;
    #pragma unroll
    for (int i = 0; i < 4; i++)
        acc[i] = fmaxf(acc[i] * di + __ldg(bp + i), 0.0f) * ic;
    #pragma unroll
    for (int i = 0; i < 4; i++)
        acc[4 + i] = fmaxf(acc[4 + i] * di + __ldg(bp + 128 + i), 0.0f) * ic;
    float* ps = g_pool_sum + (size_t)s * H;
    red_add_v4(ps + 4 * lane,       acc[0], acc[1], acc[2], acc[3]);
    red_add_v4(ps + 128 + 4 * lane, acc[4], acc[5], acc[6], acc[7]);
}

// ---------------------------------------------------------------------------
// glob gather: 4 warps per node = (channel-half x edge-segment); segment
// partials combine via smem; relu+reduce to gemb; last block does FC.
// ---------------------------------------------------------------------------
__global__ __launch_bounds__(512) void k_gather_glob(const float4* __restrict__ h,
                                                     const float* __restrict__ bias,
                                                     const float* __restrict__ fc_W,
                                                     const float* __restrict__ fc_b,
                                                     float* __restrict__ out,
                                                     int N, float inv_n) {
    __shared__ float sh[H];
    __shared__ float4 comb[16][32];
    __shared__ float ge[H];
    __shared__ int s_last;
    int t = threadIdx.x;
    if (t < H) sh[t] = 0.0f;
    __syncthreads();

    int w = t >> 5;
    int lane = t & 31;
    int gidx = blockIdx.x * 16 + w;
    int node = gidx >> 2;
    int half = (gidx >> 1) & 1;
    int seg  = gidx & 1;
    bool active = (node < N);
    int fo = half * 32 + lane;

    float4 acc = make_float4(0.0f, 0.0f, 0.0f, 0.0f);
    if (active) {
        int base = g_off_glob[node];
        int end  = g_off_glob[node + 1];
        int hl = (end - base + 1) >> 1;
        int s0 = base + seg * hl;
        int s1 = seg ? end : (base + hl);
        const int* srcs = g_srcs_glob;

        if (seg == 0) acc = __ldg(h + (size_t)node * 64 + fo);

        int e = s0;
        for (; e + 8 <= s1; e += 8) {
            int r0 = __ldg(&srcs[e + 0]);
            int r1 = __ldg(&srcs[e + 1]);
            int r2 = __ldg(&srcs[e + 2]);
            int r3 = __ldg(&srcs[e + 3]);
            int r4 = __ldg(&srcs[e + 4]);
            int r5 = __ldg(&srcs[e + 5]);
            int r6 = __ldg(&srcs[e + 6]);
            int r7 = __ldg(&srcs[e + 7]);
            float4 v0 = __ldg(h + (size_t)r0 * 64 + fo);
            float4 v1 = __ldg(h + (size_t)r1 * 64 + fo);
            float4 v2 = __ldg(h + (size_t)r2 * 64 + fo);
            float4 v3 = __ldg(h + (size_t)r3 * 64 + fo);
            float4 v4 = __ldg(h + (size_t)r4 * 64 + fo);
            float4 v5 = __ldg(h + (size_t)r5 * 64 + fo);
            float4 v6 = __ldg(h + (size_t)r6 * 64 + fo);
            float4 v7 = __ldg(h + (size_t)r7 * 64 + fo);
            acc.x += v0.x + v1.x + v2.x + v3.x + v4.x + v5.x + v6.x + v7.x;
            acc.y += v0.y + v1.y + v2.y + v3.y + v4.y + v5.y + v6.y + v7.y;
            acc.z += v0.z + v1.z + v2.z + v3.z + v4.z + v5.z + v6.z + v7.z;
            acc.w += v0.w + v1.w + v2.w + v3.w + v4.w + v5.w + v6.w + v7.w;
        }
        for (; e < s1; e++) {
            int r = __ldg(&srcs[e]);
            float4 v = __ldg(h + (size_t)r * 64 + fo);
            acc.x += v.x; acc.y += v.y; acc.z += v.z; acc.w += v.w;
        }
    }

    if (seg == 1) comb[w][lane] = acc;
    __syncthreads();

    if (seg == 0 && active) {
        float4 o = comb[w + 1][lane];
        acc.x += o.x; acc.y += o.y; acc.z += o.z; acc.w += o.w;
        float di = g_dinv_glob[node];
        int ch = 4 * fo;
        const float* bp = bias + ch;
        atomicAdd(&sh[ch + 0], fmaxf(acc.x * di + __ldg(bp + 0), 0.0f));
        atomicAdd(&sh[ch + 1], fmaxf(acc.y * di + __ldg(bp + 1), 0.0f));
        atomicAdd(&sh[ch + 2], fmaxf(acc.z * di + __ldg(bp + 2), 0.0f));
        atomicAdd(&sh[ch + 3], fmaxf(acc.w * di + __ldg(bp + 3), 0.0f));
    }
    __syncthreads();
    if (t < H) atomicAdd(&g_gemb[t], sh[t]);

    // last-block fused FC
    if (t == 0) {
        __threadfence();
        int p = atomicAdd(&g_done, 1);
        s_last = (p == (int)gridDim.x - 1) ? 1 : 0;
    }
    __syncthreads();
    if (s_last) {
        if (t < H) ge[t] = __ldcg(&g_gemb[t]) * inv_n;
        __syncthreads();
        if (t < H) {
            float s = 0.0f;
            #pragma unroll 8
            for (int f = 0; f < H; f++) s += ge[f] * fc_W[t * H + f];
            out[t] = s + fc_b[t];
        }
    }
}

// hs_glob[sub_index[g]] += pooledW[g] * dinv_glob[node]
__global__ void k_inject(const int* __restrict__ sub_index, int s) {
    int i = blockIdx.x * blockDim.x + threadIdx.x;
    if (i < s * 64) {
        int g  = i >> 6;
        int f4 = i & 63;
        int node = sub_index[g];
        float di = g_dinv_glob[node];
        float4 v = ((const float4*)g_pooledW)[i];
        red_add_v4(&g_h_glob[(size_t)node * H + 4 * f4],
                   v.x * di, v.y * di, v.z * di, v.w * di);
    }
}

// ---------------------------------------------------------------------------
extern "C" void kernel_launch(void* const* d_in, const int* in_sizes, int n_in,
                              void* d_out, int out_size) {
    const float* x_sub      = (const float*)d_in[0];
    const int*   ei_sub     = (const int*)  d_in[1];
    const int*   batch_sub  = (const int*)  d_in[2];
    const int*   sub_index  = (const int*)  d_in[3];
    const float* x_glob     = (const float*)d_in[4];
    const int*   ei_glob    = (const int*)  d_in[5];
    const float* W_sub      = (const float*)d_in[7];
    const float* b_sub      = (const float*)d_in[8];
    const float* W_glob     = (const float*)d_in[9];
    const float* b_glob     = (const float*)d_in[10];
    const float* fc_W       = (const float*)d_in[11];
    const float* fc_b       = (const float*)d_in[12];
    float* out = (float*)d_out;

    const int n_sub  = in_sizes[0] / H;
    const int E_sub  = in_sizes[1] / 2;
    const int S      = in_sizes[3];
    const int n_glob = in_sizes[4] / H;
    const int E_glob = in_sizes[5] / 2;

    const int* rows_sub  = ei_sub;
    const int* cols_sub  = ei_sub + E_sub;
    const int* rows_glob = ei_glob;
    const int* cols_glob = ei_glob + E_glob;

    float* h_sub   ; cudaGetSymbolAddress((void**)&h_sub,    g_h_sub);
    float* h_glob  ; cudaGetSymbolAddress((void**)&h_glob,   g_h_glob);
    float* pooledW ; cudaGetSymbolAddress((void**)&pooledW,  g_pooledW);
    float* psum    ; cudaGetSymbolAddress((void**)&psum,     g_pool_sum);
    float* dinv_sub ; cudaGetSymbolAddress((void**)&dinv_sub,  g_dinv_sub);
    float* dinv_glob; cudaGetSymbolAddress((void**)&dinv_glob, g_dinv_glob);

    cudaFuncSetAttribute(k_mma, cudaFuncAttributeMaxDynamicSharedMemorySize, MMA_SMEM);

    static cudaStream_t s_sort = nullptr, s_glob = nullptr;
    static cudaEvent_t evRoot = nullptr, evSort = nullptr, evGlobM = nullptr;
    if (!s_sort) {
        cudaStreamCreateWithFlags(&s_sort, cudaStreamNonBlocking);
        cudaStreamCreateWithFlags(&s_glob, cudaStreamNonBlocking);
        cudaEventCreateWithFlags(&evRoot,  cudaEventDisableTiming);
        cudaEventCreateWithFlags(&evSort,  cudaEventDisableTiming);
        cudaEventCreateWithFlags(&evGlobM, cudaEventDisableTiming);
    }

    const int T = 256;
    const int NB_sub  = n_sub  / 256;
    const int NB_glob = n_glob / 256;

    // ---- serial prologue on capture stream ----
    {
        int span = S * H;
        if (n_glob > span) span = n_glob;
        k_init<<<(span + T - 1) / T, T>>>(n_sub, n_glob, S);
    }
    k_count_all<<<(E_glob + T - 1) / T, T>>>(cols_sub, E_sub, cols_glob, E_glob,
                                             batch_sub, n_sub);
    k_dinv<<<(n_glob + T - 1) / T, T>>>(n_sub, n_glob);
    cudaEventRecord(evRoot, 0);

    // ---- branch A (s_sort): counting sort ----
    cudaStreamWaitEvent(s_sort, evRoot, 0);
    k_blocksum_all<<<NB_sub + NB_glob, 256, 0, s_sort>>>(NB_sub);
    k_scan_bsum_all<<<2, 256, 0, s_sort>>>(NB_sub, NB_glob);
    k_scan_chunks_all<<<NB_sub + NB_glob, 256, 0, s_sort>>>(NB_sub, n_sub, n_glob);
    k_bucket_all<<<(E_sub + E_glob + T - 1) / T, T, 0, s_sort>>>(rows_sub, cols_sub, E_sub,
                                                                 rows_glob, cols_glob, E_glob);
    cudaEventRecord(evSort, s_sort);

    // ---- branch B (s_glob): big glob GEMM ----
    cudaStreamWaitEvent(s_glob, evRoot, 0);
    k_mma<<<dim3(2, n_glob / 128), 256, MMA_SMEM, s_glob>>>(x_glob, W_glob, h_glob,
                                                            dinv_glob, n_glob);
    cudaEventRecord(evGlobM, s_glob);

    // ---- main stream: sub pipeline ----
    k_mma<<<dim3(2, n_sub / 128), 256, MMA_SMEM>>>(x_sub, W_sub, h_sub, dinv_sub, n_sub);
    cudaStreamWaitEvent(0, evSort, 0);
    k_gather_sub<<<(n_sub * 32 + 255) / 256, 256>>>((const float4*)h_sub, b_sub,
                                                    batch_sub, n_sub);
    k_mma<<<dim3(2, S / 128), 256, MMA_SMEM>>>(psum, W_glob, pooledW,
                                               (const float*)nullptr, S);
    // ---- join + epilogue ----
    cudaStreamWaitEvent(0, evGlobM, 0);
    k_inject<<<(S * 64 + T - 1) / T, T>>>(sub_index, S);
    {
        int warps = n_glob * 4;                 // (node, half, seg)
        int blocks = (warps + 15) / 16;         // 16 warps per 512-thread block
        k_gather_glob<<<blocks, 512>>>((const float4*)h_glob, b_glob,
                                       fc_W, fc_b, out, n_glob,
                                       1.0f / (float)n_glob);
    }
}

// round 11
// speedup vs baseline: 1.1313x; 1.1313x over previous
#include <cuda_runtime.h>
#include <cuda_bf16.h>
#include <cstdint>

// ---------------------------------------------------------------------------
// GCNWithSubgraphs: gather-based, cp.async tf32 MMA GEMMs (dinv-prescaled
// fp32 output), pure-sum gathers processed in descending-degree node order
// (degree-bucketed permutation), stream-forked capture graph.
// ---------------------------------------------------------------------------

#define H 256
#define MAX_NSUB  32768
#define MAX_NGLOB 65536
#define MAX_S     1024
#define MAX_ESUB  262144
#define MAX_EGLOB 1048576

__device__ float g_h_sub[MAX_NSUB * H];
__device__ float g_h_glob[MAX_NGLOB * H];
__device__ float g_pooledW[MAX_S * H];
__device__ float g_pool_sum[MAX_S * H];
__device__ float g_pool_cnt[MAX_S];
__device__ float g_gemb[H];

__device__ int   g_cnt_sub[MAX_NSUB];
__device__ int   g_off_sub[MAX_NSUB + 1];
__device__ int   g_cur_sub[MAX_NSUB];
__device__ float g_dinv_sub[MAX_NSUB];
__device__ int   g_srcs_sub[MAX_ESUB];
__device__ int   g_perm_sub[MAX_NSUB];

__device__ int   g_cnt_glob[MAX_NGLOB];
__device__ int   g_off_glob[MAX_NGLOB + 1];
__device__ int   g_cur_glob[MAX_NGLOB];
__device__ float g_dinv_glob[MAX_NGLOB];
__device__ int   g_srcs_glob[MAX_EGLOB];
__device__ int   g_perm_glob[MAX_NGLOB];

__device__ int   g_bsum_sub[256];
__device__ int   g_bsum_glob[256];
__device__ int   g_hist[512];     // [0:256) sub, [256:512) glob; desc-degree bins

__device__ __forceinline__ void red_add_v4(float* a, float v0, float v1, float v2, float v3) {
    asm volatile("red.global.add.v4.f32 [%0], {%1,%2,%3,%4};"
                 :: "l"(a), "f"(v0), "f"(v1), "f"(v2), "f"(v3)
                 : "memory");
}

__device__ __forceinline__ void cp_async16(void* smem_dst, const void* gmem_src) {
    uint32_t s = (uint32_t)__cvta_generic_to_shared(smem_dst);
    asm volatile("cp.async.cg.shared.global [%0], [%1], 16;" :: "r"(s), "l"(gmem_src));
}
__device__ __forceinline__ void cp_commit() {
    asm volatile("cp.async.commit_group;" ::: "memory");
}
template <int N>
__device__ __forceinline__ void cp_wait() {
    asm volatile("cp.async.wait_group %0;" :: "n"(N) : "memory");
}

// ---------------------------------------------------------------------------
__global__ void k_init(int n_sub, int n_glob, int s) {
    int i = blockIdx.x * blockDim.x + threadIdx.x;
    if (i < n_sub)  g_cnt_sub[i]  = 0;
    if (i < n_glob) g_cnt_glob[i] = 0;
    if (i < s * H)  g_pool_sum[i] = 0.0f;
    if (i < s)      g_pool_cnt[i] = 0.0f;
    if (i < H)      g_gemb[i]     = 0.0f;
    if (i < 512)    g_hist[i]     = 0;
}

__global__ void k_count_all(const int* __restrict__ cols_sub, int E_sub,
                            const int* __restrict__ cols_glob, int E_glob,
                            const int* __restrict__ batch, int n_sub) {
    int i = blockIdx.x * blockDim.x + threadIdx.x;
    if (i < E_glob) atomicAdd(&g_cnt_glob[cols_glob[i]], 1);
    if (i < E_sub)  atomicAdd(&g_cnt_sub[cols_sub[i]], 1);
    if (i < n_sub)  atomicAdd(&g_pool_cnt[batch[i]], 1.0f);
}

__global__ void k_dinv(int n_sub, int n_glob) {
    int i = blockIdx.x * blockDim.x + threadIdx.x;
    if (i < n_sub)  g_dinv_sub[i]  = rsqrtf((float)(g_cnt_sub[i] + 1));
    if (i < n_glob) g_dinv_glob[i] = rsqrtf((float)(g_cnt_glob[i] + 1));
}

// ---- degree-bucketed node permutation (descending degree) ----
__global__ void k_hist_all(int n_sub, int n_glob) {
    int i = blockIdx.x * blockDim.x + threadIdx.x;
    if (i < n_sub)  atomicAdd(&g_hist[255 - min(g_cnt_sub[i], 255)], 1);
    if (i < n_glob) atomicAdd(&g_hist[256 + 255 - min(g_cnt_glob[i], 255)], 1);
}

__global__ void k_scan_hist() {               // 2 blocks x 256: exclusive scan per half
    __shared__ int sh[256];
    int t = threadIdx.x;
    int* hist = g_hist + blockIdx.x * 256;
    int c = hist[t];
    sh[t] = c;
    __syncthreads();
    #pragma unroll
    for (int d = 1; d < 256; d <<= 1) {
        int v = (t >= d) ? sh[t - d] : 0;
        __syncthreads();
        sh[t] += v;
        __syncthreads();
    }
    hist[t] = sh[t] - c;                      // exclusive; becomes running cursor
}

__global__ void k_permute_all(int n_sub, int n_glob) {
    int i = blockIdx.x * blockDim.x + threadIdx.x;
    if (i < n_sub) {
        int b = 255 - min(g_cnt_sub[i], 255);
        int p = atomicAdd(&g_hist[b], 1);
        g_perm_sub[p] = i;
    }
    if (i < n_glob) {
        int b = 255 - min(g_cnt_glob[i], 255);
        int p = atomicAdd(&g_hist[256 + b], 1);
        g_perm_glob[p] = i;
    }
}

// ---------------------------------------------------------------------------
// tf32 MMA GEMM: C[M,256](f32) = (A[M,256] @ B[256,256]) * rowscale
// cp.async double-buffered, no STS, no cvt. 128x128 block, 256 thr, BK=32.
// ---------------------------------------------------------------------------
#define ASP 36
#define BSP 136
#define ASZ (128 * ASP)
#define BSZ (32 * BSP)
#define STG (ASZ + BSZ)
#define MMA_SMEM (2 * STG * 4)

__global__ __launch_bounds__(256) void k_mma(const float* __restrict__ A,
                                             const float* __restrict__ B,
                                             float* __restrict__ C,
                                             const float* __restrict__ rowscale, int M) {
    extern __shared__ float sm[];

    const int tid  = threadIdx.x;
    const int lane = tid & 31;
    const int wid  = tid >> 5;
    const int warpM = wid >> 1;
    const int warpN = wid & 1;
    const int g  = lane >> 2;
    const int tg = lane & 3;
    const int mb = warpM * 32;
    const int nb = warpN * 64;

    const int bc = blockIdx.x;
    const int br = blockIdx.y;

    const float* Ab = A + (size_t)br * 128 * H;
    const float* Bb = B + bc * 128;

    float c[2][8][4];
    #pragma unroll
    for (int mt = 0; mt < 2; mt++)
        #pragma unroll
        for (int nt = 0; nt < 8; nt++)
            #pragma unroll
            for (int i = 0; i < 4; i++) c[mt][nt][i] = 0.0f;

    auto load_tiles = [&](int stage, int k0) {
        float* as = sm + stage * STG;
        float* bs = as + ASZ;
        #pragma unroll
        for (int p = 0; p < 4; p++) {
            int idx = tid + p * 256;
            int row = idx >> 3;
            int c4  = (idx & 7) * 4;
            cp_async16(&as[row * ASP + c4], Ab + (size_t)row * H + k0 + c4);
        }
        #pragma unroll
        for (int p = 0; p < 4; p++) {
            int idx = tid + p * 256;
            int row = idx >> 5;
            int c4  = (idx & 31) * 4;
            cp_async16(&bs[row * BSP + c4], Bb + (size_t)(k0 + row) * H + c4);
        }
        cp_commit();
    };

    load_tiles(0, 0);

    const int NIT = H / 32;
    for (int it = 0; it < NIT; it++) {
        if (it + 1 < NIT) {
            load_tiles((it + 1) & 1, (it + 1) * 32);
            cp_wait<1>();
        } else {
            cp_wait<0>();
        }
        __syncthreads();

        const uint32_t* as = (const uint32_t*)(sm + (it & 1) * STG);
        const uint32_t* bs = as + ASZ;

        #pragma unroll
        for (int kk = 0; kk < 4; kk++) {
            const int k = kk * 8;
            uint32_t a[2][4];
            #pragma unroll
            for (int mt = 0; mt < 2; mt++) {
                int m = mb + mt * 16 + g;
                a[mt][0] = as[(size_t)m * ASP + k + tg];
                a[mt][1] = as[(size_t)(m + 8) * ASP + k + tg];
                a[mt][2] = as[(size_t)m * ASP + k + tg + 4];
                a[mt][3] = as[(size_t)(m + 8) * ASP + k + tg + 4];
            }
            #pragma unroll
            for (int nt = 0; nt < 8; nt++) {
                int n = nb + nt * 8 + g;
                uint32_t b0 = bs[(size_t)(k + tg) * BSP + n];
                uint32_t b1 = bs[(size_t)(k + tg + 4) * BSP + n];
                #pragma unroll
                for (int mt = 0; mt < 2; mt++) {
                    asm volatile(
                        "mma.sync.aligned.m16n8k8.row.col.f32.tf32.tf32.f32 "
                        "{%0,%1,%2,%3}, {%4,%5,%6,%7}, {%8,%9}, {%0,%1,%2,%3};"
                        : "+f"(c[mt][nt][0]), "+f"(c[mt][nt][1]),
                          "+f"(c[mt][nt][2]), "+f"(c[mt][nt][3])
                        : "r"(a[mt][0]), "r"(a[mt][1]), "r"(a[mt][2]), "r"(a[mt][3]),
                          "r"(b0), "r"(b1));
                }
            }
        }
        __syncthreads();
    }

    float* Cb = C + (size_t)br * 128 * H + bc * 128;
    #pragma unroll
    for (int mt = 0; mt < 2; mt++) {
        int r0 = mb + mt * 16 + g;
        float s0 = 1.0f, s1 = 1.0f;
        if (rowscale) {
            s0 = __ldg(&rowscale[br * 128 + r0]);
            s1 = __ldg(&rowscale[br * 128 + r0 + 8]);
        }
        #pragma unroll
        for (int nt = 0; nt < 8; nt++) {
            int col = nb + nt * 8 + 2 * tg;
            *(float2*)(Cb + (size_t)r0 * H + col)       = make_float2(c[mt][nt][0] * s0, c[mt][nt][1] * s0);
            *(float2*)(Cb + (size_t)(r0 + 8) * H + col) = make_float2(c[mt][nt][2] * s1, c[mt][nt][3] * s1);
        }
    }
}

// ---------------------------------------------------------------------------
// counting sort (both graphs batched)
// ---------------------------------------------------------------------------
__global__ void k_blocksum_all(int NB_sub) {
    __shared__ int sh[256];
    int t = threadIdx.x;
    bool is_sub = (blockIdx.x < NB_sub);
    const int* cnt = is_sub ? g_cnt_sub : g_cnt_glob;
    int cb = is_sub ? blockIdx.x : blockIdx.x - NB_sub;
    sh[t] = cnt[cb * 256 + t];
    __syncthreads();
    #pragma unroll
    for (int s = 128; s > 0; s >>= 1) {
        if (t < s) sh[t] += sh[t + s];
        __syncthreads();
    }
    if (t == 0) (is_sub ? g_bsum_sub : g_bsum_glob)[cb] = sh[0];
}

__global__ void k_scan_bsum_all(int NB_sub, int NB_glob) {
    __shared__ int sh[256];
    int t = threadIdx.x;
    int* bsum = (blockIdx.x == 0) ? g_bsum_sub : g_bsum_glob;
    int NB = (blockIdx.x == 0) ? NB_sub : NB_glob;
    sh[t] = (t < NB) ? bsum[t] : 0;
    __syncthreads();
    #pragma unroll
    for (int d = 1; d < 256; d <<= 1) {
        int v = (t >= d) ? sh[t - d] : 0;
        __syncthreads();
        sh[t] += v;
        __syncthreads();
    }
    int ex = (t == 0) ? 0 : sh[t - 1];
    if (t < NB) bsum[t] = ex;
}

__global__ void k_scan_chunks_all(int NB_sub, int n_sub, int n_glob) {
    __shared__ int sh[256];
    int t = threadIdx.x;
    bool is_sub = (blockIdx.x < NB_sub);
    const int* cnt = is_sub ? g_cnt_sub : g_cnt_glob;
    const int* bsum = is_sub ? g_bsum_sub : g_bsum_glob;
    int* off = is_sub ? g_off_sub : g_off_glob;
    int* cur = is_sub ? g_cur_sub : g_cur_glob;
    int N = is_sub ? n_sub : n_glob;
    int cb = is_sub ? blockIdx.x : blockIdx.x - NB_sub;
    int i = cb * 256 + t;
    int c = cnt[i];
    sh[t] = c;
    __syncthreads();
    #pragma unroll
    for (int d = 1; d < 256; d <<= 1) {
        int v = (t >= d) ? sh[t - d] : 0;
        __syncthreads();
        sh[t] += v;
        __syncthreads();
    }
    int excl = sh[t] - c + bsum[cb];
    off[i] = excl;
    cur[i] = excl;
    if (i == N - 1) off[N] = excl + c;
}

__global__ void k_bucket_all(const int* __restrict__ rows_sub,
                             const int* __restrict__ cols_sub, int E_sub,
                             const int* __restrict__ rows_glob,
                             const int* __restrict__ cols_glob, int E_glob) {
    int i = blockIdx.x * blockDim.x + threadIdx.x;
    if (i < E_sub) {
        int c = cols_sub[i];
        int p = atomicAdd(&g_cur_sub[c], 1);
        g_srcs_sub[p] = rows_sub[i];
    }
    int e = i - E_sub;
    if (e >= 0 && e < E_glob) {
        int c = cols_glob[e];
        int p = atomicAdd(&g_cur_glob[c], 1);
        g_srcs_glob[p] = rows_glob[e];
    }
}

// ---------------------------------------------------------------------------
// sub gather: warp per (degree-sorted) node; lane owns float4 {lane, lane+32}.
// ---------------------------------------------------------------------------
__device__ __forceinline__ void f4_add2(float4 v0, float4 v1, float* acc) {
    acc[0] += v0.x; acc[1] += v0.y; acc[2] += v0.z; acc[3] += v0.w;
    acc[4] += v1.x; acc[5] += v1.y; acc[6] += v1.z; acc[7] += v1.w;
}

__global__ __launch_bounds__(256) void k_gather_sub(const float4* __restrict__ h,
                                                    const float* __restrict__ bias,
                                                    const int* __restrict__ batch, int N) {
    int warp = (blockIdx.x * blockDim.x + threadIdx.x) >> 5;
    int lane = threadIdx.x & 31;
    if (warp >= N) return;
    int node = g_perm_sub[warp];

    int base = g_off_sub[node];
    int end  = g_off_sub[node + 1];
    const int* srcs = g_srcs_sub;

    float acc[8];
    {
        float4 s0 = __ldg(h + (size_t)node * 64 + lane);
        float4 s1 = __ldg(h + (size_t)node * 64 + lane + 32);
        acc[0] = s0.x; acc[1] = s0.y; acc[2] = s0.z; acc[3] = s0.w;
        acc[4] = s1.x; acc[5] = s1.y; acc[6] = s1.z; acc[7] = s1.w;
    }
    int e = base;
    for (; e + 4 <= end; e += 4) {
        int r0 = __ldg(&srcs[e + 0]);
        int r1 = __ldg(&srcs[e + 1]);
        int r2 = __ldg(&srcs[e + 2]);
        int r3 = __ldg(&srcs[e + 3]);
        float4 a0 = __ldg(h + (size_t)r0 * 64 + lane);
        float4 b0 = __ldg(h + (size_t)r0 * 64 + lane + 32);
        float4 a1 = __ldg(h + (size_t)r1 * 64 + lane);
        float4 b1 = __ldg(h + (size_t)r1 * 64 + lane + 32);
        float4 a2 = __ldg(h + (size_t)r2 * 64 + lane);
        float4 b2 = __ldg(h + (size_t)r2 * 64 + lane + 32);
        float4 a3 = __ldg(h + (size_t)r3 * 64 + lane);
        float4 b3 = __ldg(h + (size_t)r3 * 64 + lane + 32);
        f4_add2(a0, b0, acc);
        f4_add2(a1, b1, acc);
        f4_add2(a2, b2, acc);
        f4_add2(a3, b3, acc);
    }
    for (; e < end; e++) {
        int r = __ldg(&srcs[e]);
        float4 a = __ldg(h + (size_t)r * 64 + lane);
        float4 b = __ldg(h + (size_t)r * 64 + lane + 32);
        f4_add2(a, b, acc);
    }

    float di = g_dinv_sub[node];
    int s = batch[node];
    float ic = 1.0f / fmaxf(g_pool_cnt[s], 1.0f);
    const float* bp = bias + 4 * lane;
    #pragma unroll
    for (int i = 0; i < 4; i++)
        acc[i] = fmaxf(acc[i] * di + __ldg(bp + i), 0.0f) * ic;
    #pragma unroll
    for (int i = 0; i < 4; i++)
        acc[4 + i] = fmaxf(acc[4 + i] * di + __ldg(bp + 128 + i), 0.0f) * ic;
    float* ps = g_pool_sum + (size_t)s * H;
    red_add_v4(ps + 4 * lane,       acc[0], acc[1], acc[2], acc[3]);
    red_add_v4(ps + 128 + 4 * lane, acc[4], acc[5], acc[6], acc[7]);
}

// ---------------------------------------------------------------------------
// glob gather: warp per (degree-sorted node, channel-half); 8-edge batch.
// ---------------------------------------------------------------------------
__global__ __launch_bounds__(512) void k_gather_glob(const float4* __restrict__ h,
                                                     const float* __restrict__ bias, int N) {
    __shared__ float sh[H];
    int t = threadIdx.x;
    if (t < H) sh[t] = 0.0f;
    __syncthreads();

    int gwarp = (blockIdx.x * blockDim.x + t) >> 5;
    int lane = t & 31;
    int half = gwarp & 1;
    int nidx = gwarp >> 1;
    if (nidx < N) {
        int node = g_perm_glob[nidx];
        int base = g_off_glob[node];
        int end  = g_off_glob[node + 1];
        const int* srcs = g_srcs_glob;
        int fo = half * 32 + lane;

        float4 acc = __ldg(h + (size_t)node * 64 + fo);

        int e = base;
        for (; e + 8 <= end; e += 8) {
            int r0 = __ldg(&srcs[e + 0]);
            int r1 = __ldg(&srcs[e + 1]);
            int r2 = __ldg(&srcs[e + 2]);
            int r3 = __ldg(&srcs[e + 3]);
            int r4 = __ldg(&srcs[e + 4]);
            int r5 = __ldg(&srcs[e + 5]);
            int r6 = __ldg(&srcs[e + 6]);
            int r7 = __ldg(&srcs[e + 7]);
            float4 v0 = __ldg(h + (size_t)r0 * 64 + fo);
            float4 v1 = __ldg(h + (size_t)r1 * 64 + fo);
            float4 v2 = __ldg(h + (size_t)r2 * 64 + fo);
            float4 v3 = __ldg(h + (size_t)r3 * 64 + fo);
            float4 v4 = __ldg(h + (size_t)r4 * 64 + fo);
            float4 v5 = __ldg(h + (size_t)r5 * 64 + fo);
            float4 v6 = __ldg(h + (size_t)r6 * 64 + fo);
            float4 v7 = __ldg(h + (size_t)r7 * 64 + fo);
            acc.x += v0.x + v1.x + v2.x + v3.x + v4.x + v5.x + v6.x + v7.x;
            acc.y += v0.y + v1.y + v2.y + v3.y + v4.y + v5.y + v6.y + v7.y;
            acc.z += v0.z + v1.z + v2.z + v3.z + v4.z + v5.z + v6.z + v7.z;
            acc.w += v0.w + v1.w + v2.w + v3.w + v4.w + v5.w + v6.w + v7.w;
        }
        for (; e < end; e++) {
            int r = __ldg(&srcs[e]);
            float4 v = __ldg(h + (size_t)r * 64 + fo);
            acc.x += v.x; acc.y += v.y; acc.z += v.z; acc.w += v.w;
        }

        float di = g_dinv_glob[node];
        int ch = 4 * fo;
        const float* bp = bias + ch;
        atomicAdd(&sh[ch + 0], fmaxf(acc.x * di + __ldg(bp + 0), 0.0f));
        atomicAdd(&sh[ch + 1], fmaxf(acc.y * di + __ldg(bp + 1), 0.0f));
        atomicAdd(&sh[ch + 2], fmaxf(acc.z * di + __ldg(bp + 2), 0.0f));
        atomicAdd(&sh[ch + 3], fmaxf(acc.w * di + __ldg(bp + 3), 0.0f));
    }
    __syncthreads();
    if (t < H) atomicAdd(&g_gemb[t], sh[t]);
}

// hs_glob[sub_index[g]] += pooledW[g] * dinv_glob[node]
__global__ void k_inject(const int* __restrict__ sub_index, int s) {
    int i = blockIdx.x * blockDim.x + threadIdx.x;
    if (i < s * 64) {
        int g  = i >> 6;
        int f4 = i & 63;
        int node = sub_index[g];
        float di = g_dinv_glob[node];
        float4 v = ((const float4*)g_pooledW)[i];
        red_add_v4(&g_h_glob[(size_t)node * H + 4 * f4],
                   v.x * di, v.y * di, v.z * di, v.w * di);
    }
}

__global__ void k_final(const float* __restrict__ fc_W, const float* __restrict__ fc_b,
                        float* __restrict__ out, float inv_n) {
    __shared__ float ge[H];
    int t = threadIdx.x;
    ge[t] = g_gemb[t] * inv_n;
    __syncthreads();
    float s = 0.0f;
    #pragma unroll 8
    for (int f = 0; f < H; f++) s += ge[f] * fc_W[t * H + f];
    out[t] = s + fc_b[t];
}

// ---------------------------------------------------------------------------
extern "C" void kernel_launch(void* const* d_in, const int* in_sizes, int n_in,
                              void* d_out, int out_size) {
    const float* x_sub      = (const float*)d_in[0];
    const int*   ei_sub     = (const int*)  d_in[1];
    const int*   batch_sub  = (const int*)  d_in[2];
    const int*   sub_index  = (const int*)  d_in[3];
    const float* x_glob     = (const float*)d_in[4];
    const int*   ei_glob    = (const int*)  d_in[5];
    const float* W_sub      = (const float*)d_in[7];
    const float* b_sub      = (const float*)d_in[8];
    const float* W_glob     = (const float*)d_in[9];
    const float* b_glob     = (const float*)d_in[10];
    const float* fc_W       = (const float*)d_in[11];
    const float* fc_b       = (const float*)d_in[12];
    float* out = (float*)d_out;

    const int n_sub  = in_sizes[0] / H;
    const int E_sub  = in_sizes[1] / 2;
    const int S      = in_sizes[3];
    const int n_glob = in_sizes[4] / H;
    const int E_glob = in_sizes[5] / 2;

    const int* rows_sub  = ei_sub;
    const int* cols_sub  = ei_sub + E_sub;
    const int* rows_glob = ei_glob;
    const int* cols_glob = ei_glob + E_glob;

    float* h_sub   ; cudaGetSymbolAddress((void**)&h_sub,    g_h_sub);
    float* h_glob  ; cudaGetSymbolAddress((void**)&h_glob,   g_h_glob);
    float* pooledW ; cudaGetSymbolAddress((void**)&pooledW,  g_pooledW);
    float* psum    ; cudaGetSymbolAddress((void**)&psum,     g_pool_sum);
    float* dinv_sub ; cudaGetSymbolAddress((void**)&dinv_sub,  g_dinv_sub);
    float* dinv_glob; cudaGetSymbolAddress((void**)&dinv_glob, g_dinv_glob);

    cudaFuncSetAttribute(k_mma, cudaFuncAttributeMaxDynamicSharedMemorySize, MMA_SMEM);

    static cudaStream_t s_sort = nullptr, s_glob = nullptr;
    static cudaEvent_t evRoot = nullptr, evSort = nullptr, evGlobM = nullptr;
    if (!s_sort) {
        cudaStreamCreateWithFlags(&s_sort, cudaStreamNonBlocking);
        cudaStreamCreateWithFlags(&s_glob, cudaStreamNonBlocking);
        cudaEventCreateWithFlags(&evRoot,  cudaEventDisableTiming);
        cudaEventCreateWithFlags(&evSort,  cudaEventDisableTiming);
        cudaEventCreateWithFlags(&evGlobM, cudaEventDisableTiming);
    }

    const int T = 256;
    const int NB_sub  = n_sub  / 256;
    const int NB_glob = n_glob / 256;

    // ---- serial prologue on capture stream ----
    {
        int span = S * H;
        if (n_glob > span) span = n_glob;
        k_init<<<(span + T - 1) / T, T>>>(n_sub, n_glob, S);
    }
    k_count_all<<<(E_glob + T - 1) / T, T>>>(cols_sub, E_sub, cols_glob, E_glob,
                                             batch_sub, n_sub);
    k_dinv<<<(n_glob + T - 1) / T, T>>>(n_sub, n_glob);
    cudaEventRecord(evRoot, 0);

    // ---- branch A (s_sort): counting sort + degree permutation ----
    cudaStreamWaitEvent(s_sort, evRoot, 0);
    k_blocksum_all<<<NB_sub + NB_glob, 256, 0, s_sort>>>(NB_sub);
    k_scan_bsum_all<<<2, 256, 0, s_sort>>>(NB_sub, NB_glob);
    k_scan_chunks_all<<<NB_sub + NB_glob, 256, 0, s_sort>>>(NB_sub, n_sub, n_glob);
    k_bucket_all<<<(E_sub + E_glob + T - 1) / T, T, 0, s_sort>>>(rows_sub, cols_sub, E_sub,
                                                                 rows_glob, cols_glob, E_glob);
    k_hist_all<<<(n_glob + T - 1) / T, T, 0, s_sort>>>(n_sub, n_glob);
    k_scan_hist<<<2, 256, 0, s_sort>>>();
    k_permute_all<<<(n_glob + T - 1) / T, T, 0, s_sort>>>(n_sub, n_glob);
    cudaEventRecord(evSort, s_sort);

    // ---- branch B (s_glob): big glob GEMM ----
    cudaStreamWaitEvent(s_glob, evRoot, 0);
    k_mma<<<dim3(2, n_glob / 128), 256, MMA_SMEM, s_glob>>>(x_glob, W_glob, h_glob,
                                                            dinv_glob, n_glob);
    cudaEventRecord(evGlobM, s_glob);

    // ---- main stream: sub pipeline ----
    k_mma<<<dim3(2, n_sub / 128), 256, MMA_SMEM>>>(x_sub, W_sub, h_sub, dinv_sub, n_sub);
    cudaStreamWaitEvent(0, evSort, 0);
    k_gather_sub<<<(n_sub * 32 + 255) / 256, 256>>>((const float4*)h_sub, b_sub,
                                                    batch_sub, n_sub);
    k_mma<<<dim3(2, S / 128), 256, MMA_SMEM>>>(psum, W_glob, pooledW,
                                               (const float*)nullptr, S);
    // ---- join + epilogue ----
    cudaStreamWaitEvent(0, evGlobM, 0);
    k_inject<<<(S * 64 + T - 1) / T, T>>>(sub_index, S);
    k_gather_glob<<<(n_glob * 64 + 511) / 512, 512>>>((const float4*)h_glob, b_glob, n_glob);
    k_final<<<1, H>>>(fc_W, fc_b, out, 1.0f / (float)n_glob);
}

// round 12
// speedup vs baseline: 1.1858x; 1.0482x over previous
#include <cuda_runtime.h>
#include <cuda_bf16.h>
#include <cstdint>

// ---------------------------------------------------------------------------
// GCNWithSubgraphs: gather-based, 3-stage cp.async tf32 MMA GEMMs
// (dinv-prescaled fp32 output), pure-sum gathers, stream-forked graph:
//   {mma_glob} || {sort} || {mma_sub -> gather_sub -> mma_pool}  then
//   inject -> gather_glob(+fused FC).
// ---------------------------------------------------------------------------

#define H 256
#define MAX_NSUB  32768
#define MAX_NGLOB 65536
#define MAX_S     1024
#define MAX_ESUB  262144
#define MAX_EGLOB 1048576

__device__ float g_h_sub[MAX_NSUB * H];
__device__ float g_h_glob[MAX_NGLOB * H];
__device__ float g_pooledW[MAX_S * H];
__device__ float g_pool_sum[MAX_S * H];
__device__ float g_pool_cnt[MAX_S];
__device__ float g_gemb[H];
__device__ int   g_done;

__device__ int   g_cnt_sub[MAX_NSUB];
__device__ int   g_off_sub[MAX_NSUB + 1];
__device__ int   g_cur_sub[MAX_NSUB];
__device__ float g_dinv_sub[MAX_NSUB];
__device__ int   g_srcs_sub[MAX_ESUB];

__device__ int   g_cnt_glob[MAX_NGLOB];
__device__ int   g_off_glob[MAX_NGLOB + 1];
__device__ int   g_cur_glob[MAX_NGLOB];
__device__ float g_dinv_glob[MAX_NGLOB];
__device__ int   g_srcs_glob[MAX_EGLOB];

__device__ int   g_bsum_sub[256];
__device__ int   g_bsum_glob[256];

__device__ __forceinline__ void red_add_v4(float* a, float v0, float v1, float v2, float v3) {
    asm volatile("red.global.add.v4.f32 [%0], {%1,%2,%3,%4};"
                 :: "l"(a), "f"(v0), "f"(v1), "f"(v2), "f"(v3)
                 : "memory");
}

__device__ __forceinline__ void cp_async16(void* smem_dst, const void* gmem_src) {
    uint32_t s = (uint32_t)__cvta_generic_to_shared(smem_dst);
    asm volatile("cp.async.cg.shared.global [%0], [%1], 16;" :: "r"(s), "l"(gmem_src));
}
__device__ __forceinline__ void cp_commit() {
    asm volatile("cp.async.commit_group;" ::: "memory");
}
template <int N>
__device__ __forceinline__ void cp_wait() {
    asm volatile("cp.async.wait_group %0;" :: "n"(N) : "memory");
}

// ---------------------------------------------------------------------------
__global__ void k_init(int n_sub, int n_glob, int s) {
    int i = blockIdx.x * blockDim.x + threadIdx.x;
    if (i < n_sub)  g_cnt_sub[i]  = 0;
    if (i < n_glob) g_cnt_glob[i] = 0;
    if (i < s * H)  g_pool_sum[i] = 0.0f;
    if (i < s)      g_pool_cnt[i] = 0.0f;
    if (i < H)      g_gemb[i]     = 0.0f;
    if (i == 0)     g_done        = 0;
}

__global__ void k_count_all(const int* __restrict__ cols_sub, int E_sub,
                            const int* __restrict__ cols_glob, int E_glob,
                            const int* __restrict__ batch, int n_sub) {
    int i = blockIdx.x * blockDim.x + threadIdx.x;
    if (i < E_glob) atomicAdd(&g_cnt_glob[cols_glob[i]], 1);
    if (i < E_sub)  atomicAdd(&g_cnt_sub[cols_sub[i]], 1);
    if (i < n_sub)  atomicAdd(&g_pool_cnt[batch[i]], 1.0f);
}

__global__ void k_dinv(int n_sub, int n_glob) {
    int i = blockIdx.x * blockDim.x + threadIdx.x;
    if (i < n_sub)  g_dinv_sub[i]  = rsqrtf((float)(g_cnt_sub[i] + 1));
    if (i < n_glob) g_dinv_glob[i] = rsqrtf((float)(g_cnt_glob[i] + 1));
}

// ---------------------------------------------------------------------------
// tf32 MMA GEMM: C[M,256](f32) = (A[M,256] @ B[256,256]) * rowscale.
// 3-stage cp.async pipeline, one __syncthreads per k-iter, no STS, no cvt.
// Block 128x128, 256 threads, 8 warps (4x2), warp tile 32x64, m16n8k8, BK=32.
// ---------------------------------------------------------------------------
#define ASP 36
#define BSP 136
#define ASZ (128 * ASP)
#define BSZ (32 * BSP)
#define STG (ASZ + BSZ)
#define NSTAGE 3
#define MMA_SMEM (NSTAGE * STG * 4)

__global__ __launch_bounds__(256) void k_mma(const float* __restrict__ A,
                                             const float* __restrict__ B,
                                             float* __restrict__ C,
                                             const float* __restrict__ rowscale, int M) {
    extern __shared__ float sm[];

    const int tid  = threadIdx.x;
    const int lane = tid & 31;
    const int wid  = tid >> 5;
    const int warpM = wid >> 1;
    const int warpN = wid & 1;
    const int g  = lane >> 2;
    const int tg = lane & 3;
    const int mb = warpM * 32;
    const int nb = warpN * 64;

    const int bc = blockIdx.x;
    const int br = blockIdx.y;

    const float* Ab = A + (size_t)br * 128 * H;
    const float* Bb = B + bc * 128;

    float c[2][8][4];
    #pragma unroll
    for (int mt = 0; mt < 2; mt++)
        #pragma unroll
        for (int nt = 0; nt < 8; nt++)
            #pragma unroll
            for (int i = 0; i < 4; i++) c[mt][nt][i] = 0.0f;

    auto load_tiles = [&](int stage, int k0) {
        float* as = sm + stage * STG;
        float* bs = as + ASZ;
        #pragma unroll
        for (int p = 0; p < 4; p++) {
            int idx = tid + p * 256;
            int row = idx >> 3;
            int c4  = (idx & 7) * 4;
            cp_async16(&as[row * ASP + c4], Ab + (size_t)row * H + k0 + c4);
        }
        #pragma unroll
        for (int p = 0; p < 4; p++) {
            int idx = tid + p * 256;
            int row = idx >> 5;
            int c4  = (idx & 31) * 4;
            cp_async16(&bs[row * BSP + c4], Bb + (size_t)(k0 + row) * H + c4);
        }
        cp_commit();
    };

    const int NIT = H / 32;   // 8
    load_tiles(0, 0);
    load_tiles(1, 32);

    for (int it = 0; it < NIT; it++) {
        if (it < NIT - 1) cp_wait<1>();
        else              cp_wait<0>();
        __syncthreads();
        if (it + 2 < NIT) load_tiles((it + 2) % NSTAGE, (it + 2) * 32);

        const uint32_t* as = (const uint32_t*)(sm + (it % NSTAGE) * STG);
        const uint32_t* bs = as + ASZ;

        #pragma unroll
        for (int kk = 0; kk < 4; kk++) {
            const int k = kk * 8;
            uint32_t a[2][4];
            #pragma unroll
            for (int mt = 0; mt < 2; mt++) {
                int m = mb + mt * 16 + g;
                a[mt][0] = as[(size_t)m * ASP + k + tg];
                a[mt][1] = as[(size_t)(m + 8) * ASP + k + tg];
                a[mt][2] = as[(size_t)m * ASP + k + tg + 4];
                a[mt][3] = as[(size_t)(m + 8) * ASP + k + tg + 4];
            }
            #pragma unroll
            for (int nt = 0; nt < 8; nt++) {
                int n = nb + nt * 8 + g;
                uint32_t b0 = bs[(size_t)(k + tg) * BSP + n];
                uint32_t b1 = bs[(size_t)(k + tg + 4) * BSP + n];
                #pragma unroll
                for (int mt = 0; mt < 2; mt++) {
                    asm volatile(
                        "mma.sync.aligned.m16n8k8.row.col.f32.tf32.tf32.f32 "
                        "{%0,%1,%2,%3}, {%4,%5,%6,%7}, {%8,%9}, {%0,%1,%2,%3};"
                        : "+f"(c[mt][nt][0]), "+f"(c[mt][nt][1]),
                          "+f"(c[mt][nt][2]), "+f"(c[mt][nt][3])
                        : "r"(a[mt][0]), "r"(a[mt][1]), "r"(a[mt][2]), "r"(a[mt][3]),
                          "r"(b0), "r"(b1));
                }
            }
        }
        __syncthreads();
    }

    float* Cb = C + (size_t)br * 128 * H + bc * 128;
    #pragma unroll
    for (int mt = 0; mt < 2; mt++) {
        int r0 = mb + mt * 16 + g;
        float s0 = 1.0f, s1 = 1.0f;
        if (rowscale) {
            s0 = __ldg(&rowscale[br * 128 + r0]);
            s1 = __ldg(&rowscale[br * 128 + r0 + 8]);
        }
        #pragma unroll
        for (int nt = 0; nt < 8; nt++) {
            int col = nb + nt * 8 + 2 * tg;
            *(float2*)(Cb + (size_t)r0 * H + col)       = make_float2(c[mt][nt][0] * s0, c[mt][nt][1] * s0);
            *(float2*)(Cb + (size_t)(r0 + 8) * H + col) = make_float2(c[mt][nt][2] * s1, c[mt][nt][3] * s1);
        }
    }
}

// ---------------------------------------------------------------------------
// counting sort (both graphs batched)
// ---------------------------------------------------------------------------
__global__ void k_blocksum_all(int NB_sub) {
    __shared__ int sh[256];
    int t = threadIdx.x;
    bool is_sub = (blockIdx.x < NB_sub);
    const int* cnt = is_sub ? g_cnt_sub : g_cnt_glob;
    int cb = is_sub ? blockIdx.x : blockIdx.x - NB_sub;
    sh[t] = cnt[cb * 256 + t];
    __syncthreads();
    #pragma unroll
    for (int s = 128; s > 0; s >>= 1) {
        if (t < s) sh[t] += sh[t + s];
        __syncthreads();
    }
    if (t == 0) (is_sub ? g_bsum_sub : g_bsum_glob)[cb] = sh[0];
}

__global__ void k_scan_bsum_all(int NB_sub, int NB_glob) {
    __shared__ int sh[256];
    int t = threadIdx.x;
    int* bsum = (blockIdx.x == 0) ? g_bsum_sub : g_bsum_glob;
    int NB = (blockIdx.x == 0) ? NB_sub : NB_glob;
    sh[t] = (t < NB) ? bsum[t] : 0;
    __syncthreads();
    #pragma unroll
    for (int d = 1; d < 256; d <<= 1) {
        int v = (t >= d) ? sh[t - d] : 0;
        __syncthreads();
        sh[t] += v;
        __syncthreads();
    }
    int ex = (t == 0) ? 0 : sh[t - 1];
    if (t < NB) bsum[t] = ex;
}

__global__ void k_scan_chunks_all(int NB_sub, int n_sub, int n_glob) {
    __shared__ int sh[256];
    int t = threadIdx.x;
    bool is_sub = (blockIdx.x < NB_sub);
    const int* cnt = is_sub ? g_cnt_sub : g_cnt_glob;
    const int* bsum = is_sub ? g_bsum_sub : g_bsum_glob;
    int* off = is_sub ? g_off_sub : g_off_glob;
    int* cur = is_sub ? g_cur_sub : g_cur_glob;
    int N = is_sub ? n_sub : n_glob;
    int cb = is_sub ? blockIdx.x : blockIdx.x - NB_sub;
    int i = cb * 256 + t;
    int c = cnt[i];
    sh[t] = c;
    __syncthreads();
    #pragma unroll
    for (int d = 1; d < 256; d <<= 1) {
        int v = (t >= d) ? sh[t - d] : 0;
        __syncthreads();
        sh[t] += v;
        __syncthreads();
    }
    int excl = sh[t] - c + bsum[cb];
    off[i] = excl;
    cur[i] = excl;
    if (i == N - 1) off[N] = excl + c;
}

__global__ void k_bucket_all(const int* __restrict__ rows_sub,
                             const int* __restrict__ cols_sub, int E_sub,
                             const int* __restrict__ rows_glob,
                             const int* __restrict__ cols_glob, int E_glob) {
    int i = blockIdx.x * blockDim.x + threadIdx.x;
    if (i < E_sub) {
        int c = cols_sub[i];
        int p = atomicAdd(&g_cur_sub[c], 1);
        g_srcs_sub[p] = rows_sub[i];
    }
    int e = i - E_sub;
    if (e >= 0 && e < E_glob) {
        int c = cols_glob[e];
        int p = atomicAdd(&g_cur_glob[c], 1);
        g_srcs_glob[p] = rows_glob[e];
    }
}

// ---------------------------------------------------------------------------
// sub gather: warp per node; lane owns float4 {lane, lane+32}; 4-edge batch.
// ---------------------------------------------------------------------------
__device__ __forceinline__ void f4_add2(float4 v0, float4 v1, float* acc) {
    acc[0] += v0.x; acc[1] += v0.y; acc[2] += v0.z; acc[3] += v0.w;
    acc[4] += v1.x; acc[5] += v1.y; acc[6] += v1.z; acc[7] += v1.w;
}

__global__ __launch_bounds__(256) void k_gather_sub(const float4* __restrict__ h,
                                                    const float* __restrict__ bias,
                                                    const int* __restrict__ batch, int N) {
    int warp = (blockIdx.x * blockDim.x + threadIdx.x) >> 5;
    int lane = threadIdx.x & 31;
    if (warp >= N) return;

    int base = g_off_sub[warp];
    int end  = g_off_sub[warp + 1];
    const int* srcs = g_srcs_sub;

    float acc[8];
    {
        float4 s0 = __ldg(h + (size_t)warp * 64 + lane);
        float4 s1 = __ldg(h + (size_t)warp * 64 + lane + 32);
        acc[0] = s0.x; acc[1] = s0.y; acc[2] = s0.z; acc[3] = s0.w;
        acc[4] = s1.x; acc[5] = s1.y; acc[6] = s1.z; acc[7] = s1.w;
    }
    int e = base;
    for (; e + 4 <= end; e += 4) {
        int r0 = __ldg(&srcs[e + 0]);
        int r1 = __ldg(&srcs[e + 1]);
        int r2 = __ldg(&srcs[e + 2]);
        int r3 = __ldg(&srcs[e + 3]);
        float4 a0 = __ldg(h + (size_t)r0 * 64 + lane);
        float4 b0 = __ldg(h + (size_t)r0 * 64 + lane + 32);
        float4 a1 = __ldg(h + (size_t)r1 * 64 + lane);
        float4 b1 = __ldg(h + (size_t)r1 * 64 + lane + 32);
        float4 a2 = __ldg(h + (size_t)r2 * 64 + lane);
        float4 b2 = __ldg(h + (size_t)r2 * 64 + lane + 32);
        float4 a3 = __ldg(h + (size_t)r3 * 64 + lane);
        float4 b3 = __ldg(h + (size_t)r3 * 64 + lane + 32);
        f4_add2(a0, b0, acc);
        f4_add2(a1, b1, acc);
        f4_add2(a2, b2, acc);
        f4_add2(a3, b3, acc);
    }
    for (; e < end; e++) {
        int r = __ldg(&srcs[e]);
        float4 a = __ldg(h + (size_t)r * 64 + lane);
        float4 b = __ldg(h + (size_t)r * 64 + lane + 32);
        f4_add2(a, b, acc);
    }

    float di = g_dinv_sub[warp];
    int s = batch[warp];
    float ic = 1.0f / fmaxf(g_pool_cnt[s], 1.0f);
    const float* bp = bias + 4 * lane;
    #pragma unroll
    for (int i = 0; i < 4; i++)
        acc[i] = fmaxf(acc[i] * di + __ldg(bp + i), 0.0f) * ic;
    #pragma unroll
    for (int i = 0; i < 4; i++)
        acc[4 + i] = fmaxf(acc[4 + i] * di + __ldg(bp + 128 + i), 0.0f) * ic;
    float* ps = g_pool_sum + (size_t)s * H;
    red_add_v4(ps + 4 * lane,       acc[0], acc[1], acc[2], acc[3]);
    red_add_v4(ps + 128 + 4 * lane, acc[4], acc[5], acc[6], acc[7]);
}

// ---------------------------------------------------------------------------
// glob gather: warp per (node, channel-half); 8-edge batch; fused final FC.
// ---------------------------------------------------------------------------
__global__ __launch_bounds__(512) void k_gather_glob(const float4* __restrict__ h,
                                                     const float* __restrict__ bias,
                                                     const float* __restrict__ fc_W,
                                                     const float* __restrict__ fc_b,
                                                     float* __restrict__ out,
                                                     int N, float inv_n) {
    __shared__ float sh[H];
    __shared__ float ge[H];
    __shared__ int s_last;
    int t = threadIdx.x;
    if (t < H) sh[t] = 0.0f;
    __syncthreads();

    int gwarp = (blockIdx.x * blockDim.x + t) >> 5;
    int lane = t & 31;
    int node = gwarp >> 1;
    int half = gwarp & 1;
    if (node < N) {
        int base = g_off_glob[node];
        int end  = g_off_glob[node + 1];
        const int* srcs = g_srcs_glob;
        int fo = half * 32 + lane;

        float4 acc = __ldg(h + (size_t)node * 64 + fo);

        int e = base;
        for (; e + 8 <= end; e += 8) {
            int r0 = __ldg(&srcs[e + 0]);
            int r1 = __ldg(&srcs[e + 1]);
            int r2 = __ldg(&srcs[e + 2]);
            int r3 = __ldg(&srcs[e + 3]);
            int r4 = __ldg(&srcs[e + 4]);
            int r5 = __ldg(&srcs[e + 5]);
            int r6 = __ldg(&srcs[e + 6]);
            int r7 = __ldg(&srcs[e + 7]);
            float4 v0 = __ldg(h + (size_t)r0 * 64 + fo);
            float4 v1 = __ldg(h + (size_t)r1 * 64 + fo);
            float4 v2 = __ldg(h + (size_t)r2 * 64 + fo);
            float4 v3 = __ldg(h + (size_t)r3 * 64 + fo);
            float4 v4 = __ldg(h + (size_t)r4 * 64 + fo);
            float4 v5 = __ldg(h + (size_t)r5 * 64 + fo);
            float4 v6 = __ldg(h + (size_t)r6 * 64 + fo);
            float4 v7 = __ldg(h + (size_t)r7 * 64 + fo);
            acc.x += v0.x + v1.x + v2.x + v3.x + v4.x + v5.x + v6.x + v7.x;
            acc.y += v0.y + v1.y + v2.y + v3.y + v4.y + v5.y + v6.y + v7.y;
            acc.z += v0.z + v1.z + v2.z + v3.z + v4.z + v5.z + v6.z + v7.z;
            acc.w += v0.w + v1.w + v2.w + v3.w + v4.w + v5.w + v6.w + v7.w;
        }
        for (; e < end; e++) {
            int r = __ldg(&srcs[e]);
            float4 v = __ldg(h + (size_t)r * 64 + fo);
            acc.x += v.x; acc.y += v.y; acc.z += v.z; acc.w += v.w;
        }

        float di = g_dinv_glob[node];
        int ch = 4 * fo;
        const float* bp = bias + ch;
        atomicAdd(&sh[ch + 0], fmaxf(acc.x * di + __ldg(bp + 0), 0.0f));
        atomicAdd(&sh[ch + 1], fmaxf(acc.y * di + __ldg(bp + 1), 0.0f));
        atomicAdd(&sh[ch + 2], fmaxf(acc.z * di + __ldg(bp + 2), 0.0f));
        atomicAdd(&sh[ch + 3], fmaxf(acc.w * di + __ldg(bp + 3), 0.0f));
    }
    __syncthreads();
    if (t < H) atomicAdd(&g_gemb[t], sh[t]);

    // last-block fused FC
    if (t == 0) {
        __threadfence();
        int p = atomicAdd(&g_done, 1);
        s_last = (p == (int)gridDim.x - 1) ? 1 : 0;
    }
    __syncthreads();
    if (s_last) {
        if (t < H) ge[t] = __ldcg(&g_gemb[t]) * inv_n;
        __syncthreads();
        if (t < H) {
            float s = 0.0f;
            #pragma unroll 8
            for (int f = 0; f < H; f++) s += ge[f] * fc_W[t * H + f];
            out[t] = s + fc_b[t];
        }
    }
}

// hs_glob[sub_index[g]] += pooledW[g] * dinv_glob[node]
__global__ void k_inject(const int* __restrict__ sub_index, int s) {
    int i = blockIdx.x * blockDim.x + threadIdx.x;
    if (i < s * 64) {
        int g  = i >> 6;
        int f4 = i & 63;
        int node = sub_index[g];
        float di = g_dinv_glob[node];
        float4 v = ((const float4*)g_pooledW)[i];
        red_add_v4(&g_h_glob[(size_t)node * H + 4 * f4],
                   v.x * di, v.y * di, v.z * di, v.w * di);
    }
}

// ---------------------------------------------------------------------------
extern "C" void kernel_launch(void* const* d_in, const int* in_sizes, int n_in,
                              void* d_out, int out_size) {
    const float* x_sub      = (const float*)d_in[0];
    const int*   ei_sub     = (const int*)  d_in[1];
    const int*   batch_sub  = (const int*)  d_in[2];
    const int*   sub_index  = (const int*)  d_in[3];
    const float* x_glob     = (const float*)d_in[4];
    const int*   ei_glob    = (const int*)  d_in[5];
    const float* W_sub      = (const float*)d_in[7];
    const float* b_sub      = (const float*)d_in[8];
    const float* W_glob     = (const float*)d_in[9];
    const float* b_glob     = (const float*)d_in[10];
    const float* fc_W       = (const float*)d_in[11];
    const float* fc_b       = (const float*)d_in[12];
    float* out = (float*)d_out;

    const int n_sub  = in_sizes[0] / H;
    const int E_sub  = in_sizes[1] / 2;
    const int S      = in_sizes[3];
    const int n_glob = in_sizes[4] / H;
    const int E_glob = in_sizes[5] / 2;

    const int* rows_sub  = ei_sub;
    const int* cols_sub  = ei_sub + E_sub;
    const int* rows_glob = ei_glob;
    const int* cols_glob = ei_glob + E_glob;

    float* h_sub   ; cudaGetSymbolAddress((void**)&h_sub,    g_h_sub);
    float* h_glob  ; cudaGetSymbolAddress((void**)&h_glob,   g_h_glob);
    float* pooledW ; cudaGetSymbolAddress((void**)&pooledW,  g_pooledW);
    float* psum    ; cudaGetSymbolAddress((void**)&psum,     g_pool_sum);
    float* dinv_sub ; cudaGetSymbolAddress((void**)&dinv_sub,  g_dinv_sub);
    float* dinv_glob; cudaGetSymbolAddress((void**)&dinv_glob, g_dinv_glob);

    cudaFuncSetAttribute(k_mma, cudaFuncAttributeMaxDynamicSharedMemorySize, MMA_SMEM);

    static cudaStream_t s_sort = nullptr, s_glob = nullptr;
    static cudaEvent_t evRoot = nullptr, evSort = nullptr, evGlobM = nullptr;
    if (!s_sort) {
        cudaStreamCreateWithFlags(&s_sort, cudaStreamNonBlocking);
        cudaStreamCreateWithFlags(&s_glob, cudaStreamNonBlocking);
        cudaEventCreateWithFlags(&evRoot,  cudaEventDisableTiming);
        cudaEventCreateWithFlags(&evSort,  cudaEventDisableTiming);
        cudaEventCreateWithFlags(&evGlobM, cudaEventDisableTiming);
    }

    const int T = 256;
    const int NB_sub  = n_sub  / 256;
    const int NB_glob = n_glob / 256;

    // ---- serial prologue on capture stream ----
    {
        int span = S * H;
        if (n_glob > span) span = n_glob;
        k_init<<<(span + T - 1) / T, T>>>(n_sub, n_glob, S);
    }
    k_count_all<<<(E_glob + T - 1) / T, T>>>(cols_sub, E_sub, cols_glob, E_glob,
                                             batch_sub, n_sub);
    k_dinv<<<(n_glob + T - 1) / T, T>>>(n_sub, n_glob);
    cudaEventRecord(evRoot, 0);

    // ---- branch A (s_sort): counting sort ----
    cudaStreamWaitEvent(s_sort, evRoot, 0);
    k_blocksum_all<<<NB_sub + NB_glob, 256, 0, s_sort>>>(NB_sub);
    k_scan_bsum_all<<<2, 256, 0, s_sort>>>(NB_sub, NB_glob);
    k_scan_chunks_all<<<NB_sub + NB_glob, 256, 0, s_sort>>>(NB_sub, n_sub, n_glob);
    k_bucket_all<<<(E_sub + E_glob + T - 1) / T, T, 0, s_sort>>>(rows_sub, cols_sub, E_sub,
                                                                 rows_glob, cols_glob, E_glob);
    cudaEventRecord(evSort, s_sort);

    // ---- branch B (s_glob): big glob GEMM ----
    cudaStreamWaitEvent(s_glob, evRoot, 0);
    k_mma<<<dim3(2, n_glob / 128), 256, MMA_SMEM, s_glob>>>(x_glob, W_glob, h_glob,
                                                            dinv_glob, n_glob);
    cudaEventRecord(evGlobM, s_glob);

    // ---- main stream: sub pipeline ----
    k_mma<<<dim3(2, n_sub / 128), 256, MMA_SMEM>>>(x_sub, W_sub, h_sub, dinv_sub, n_sub);
    cudaStreamWaitEvent(0, evSort, 0);
    k_gather_sub<<<(n_sub * 32 + 255) / 256, 256>>>((const float4*)h_sub, b_sub,
                                                    batch_sub, n_sub);
    k_mma<<<dim3(2, S / 128), 256, MMA_SMEM>>>(psum, W_glob, pooledW,
                                               (const float*)nullptr, S);
    // ---- join + epilogue ----
    cudaStreamWaitEvent(0, evGlobM, 0);
    k_inject<<<(S * 64 + T - 1) / T, T>>>(sub_index, S);
    k_gather_glob<<<(n_glob * 64 + 511) / 512, 512>>>((const float4*)h_glob, b_glob,
                                                      fc_W, fc_b, out, n_glob,
                                                      1.0f / (float)n_glob);
}

// round 13
// speedup vs baseline: 1.2100x; 1.0203x over previous
#include <cuda_runtime.h>
#include <cuda_bf16.h>
#include <cstdint>

// ---------------------------------------------------------------------------
// GCNWithSubgraphs: gather-based, 2-stage cp.async tf32 MMA GEMMs
// (dinv-prescaled fp32 output), pure-sum gathers, stream-forked graph:
//   {mma_glob} || {sort} || {mma_sub -> gather_sub}  then
//   mma_pool(epilogue injects into h_glob) -> gather_glob(+fused FC).
// ---------------------------------------------------------------------------

#define H 256
#define MAX_NSUB  32768
#define MAX_NGLOB 65536
#define MAX_S     1024
#define MAX_ESUB  262144
#define MAX_EGLOB 1048576

__device__ float g_h_sub[MAX_NSUB * H];
__device__ float g_h_glob[MAX_NGLOB * H];
__device__ float g_pool_sum[MAX_S * H];
__device__ float g_pool_cnt[MAX_S];
__device__ float g_gemb[H];
__device__ int   g_done;

__device__ int   g_cnt_sub[MAX_NSUB];
__device__ int   g_off_sub[MAX_NSUB + 1];
__device__ int   g_cur_sub[MAX_NSUB];
__device__ float g_dinv_sub[MAX_NSUB];
__device__ int   g_srcs_sub[MAX_ESUB];

__device__ int   g_cnt_glob[MAX_NGLOB];
__device__ int   g_off_glob[MAX_NGLOB + 1];
__device__ int   g_cur_glob[MAX_NGLOB];
__device__ float g_dinv_glob[MAX_NGLOB];
__device__ int   g_srcs_glob[MAX_EGLOB];

__device__ int   g_bsum_sub[256];
__device__ int   g_bsum_glob[256];

__device__ __forceinline__ void red_add_v4(float* a, float v0, float v1, float v2, float v3) {
    asm volatile("red.global.add.v4.f32 [%0], {%1,%2,%3,%4};"
                 :: "l"(a), "f"(v0), "f"(v1), "f"(v2), "f"(v3)
                 : "memory");
}
__device__ __forceinline__ void red_add_v2(float* a, float v0, float v1) {
    asm volatile("red.global.add.v2.f32 [%0], {%1,%2};"
                 :: "l"(a), "f"(v0), "f"(v1)
                 : "memory");
}

__device__ __forceinline__ void cp_async16(void* smem_dst, const void* gmem_src) {
    uint32_t s = (uint32_t)__cvta_generic_to_shared(smem_dst);
    asm volatile("cp.async.cg.shared.global [%0], [%1], 16;" :: "r"(s), "l"(gmem_src));
}
__device__ __forceinline__ void cp_commit() {
    asm volatile("cp.async.commit_group;" ::: "memory");
}
template <int N>
__device__ __forceinline__ void cp_wait() {
    asm volatile("cp.async.wait_group %0;" :: "n"(N) : "memory");
}

// ---------------------------------------------------------------------------
__global__ void k_init(int n_sub, int n_glob, int s) {
    int i = blockIdx.x * blockDim.x + threadIdx.x;
    if (i < n_sub)  g_cnt_sub[i]  = 0;
    if (i < n_glob) g_cnt_glob[i] = 0;
    if (i < s * H)  g_pool_sum[i] = 0.0f;
    if (i < s)      g_pool_cnt[i] = 0.0f;
    if (i < H)      g_gemb[i]     = 0.0f;
    if (i == 0)     g_done        = 0;
}

__global__ void k_count_all(const int* __restrict__ cols_sub, int E_sub,
                            const int* __restrict__ cols_glob, int E_glob,
                            const int* __restrict__ batch, int n_sub) {
    int i = blockIdx.x * blockDim.x + threadIdx.x;
    if (i < E_glob) atomicAdd(&g_cnt_glob[cols_glob[i]], 1);
    if (i < E_sub)  atomicAdd(&g_cnt_sub[cols_sub[i]], 1);
    if (i < n_sub)  atomicAdd(&g_pool_cnt[batch[i]], 1.0f);
}

__global__ void k_dinv(int n_sub, int n_glob) {
    int i = blockIdx.x * blockDim.x + threadIdx.x;
    if (i < n_sub)  g_dinv_sub[i]  = rsqrtf((float)(g_cnt_sub[i] + 1));
    if (i < n_glob) g_dinv_glob[i] = rsqrtf((float)(g_cnt_glob[i] + 1));
}

// ---------------------------------------------------------------------------
// tf32 MMA GEMM: 2-stage cp.async, no STS, no cvt. Block 128x128, 256 thr.
// Normal mode  (inj_idx == nullptr): C[row] = (A@B)[row] * rowscale[row]
// Inject mode  (inj_idx != nullptr): h_glob[inj_idx[row]] +=
//                                      (A@B)[row] * dinv_glob[inj_idx[row]]
// ---------------------------------------------------------------------------
#define ASP 36
#define BSP 136
#define ASZ (128 * ASP)
#define BSZ (32 * BSP)
#define STG (ASZ + BSZ)
#define MMA_SMEM (2 * STG * 4)

__global__ __launch_bounds__(256) void k_mma(const float* __restrict__ A,
                                             const float* __restrict__ B,
                                             float* __restrict__ C,
                                             const float* __restrict__ rowscale,
                                             const int* __restrict__ inj_idx, int M) {
    extern __shared__ float sm[];

    const int tid  = threadIdx.x;
    const int lane = tid & 31;
    const int wid  = tid >> 5;
    const int warpM = wid >> 1;
    const int warpN = wid & 1;
    const int g  = lane >> 2;
    const int tg = lane & 3;
    const int mb = warpM * 32;
    const int nb = warpN * 64;

    const int bc = blockIdx.x;
    const int br = blockIdx.y;

    const float* Ab = A + (size_t)br * 128 * H;
    const float* Bb = B + bc * 128;

    float c[2][8][4];
    #pragma unroll
    for (int mt = 0; mt < 2; mt++)
        #pragma unroll
        for (int nt = 0; nt < 8; nt++)
            #pragma unroll
            for (int i = 0; i < 4; i++) c[mt][nt][i] = 0.0f;

    auto load_tiles = [&](int stage, int k0) {
        float* as = sm + stage * STG;
        float* bs = as + ASZ;
        #pragma unroll
        for (int p = 0; p < 4; p++) {
            int idx = tid + p * 256;
            int row = idx >> 3;
            int c4  = (idx & 7) * 4;
            cp_async16(&as[row * ASP + c4], Ab + (size_t)row * H + k0 + c4);
        }
        #pragma unroll
        for (int p = 0; p < 4; p++) {
            int idx = tid + p * 256;
            int row = idx >> 5;
            int c4  = (idx & 31) * 4;
            cp_async16(&bs[row * BSP + c4], Bb + (size_t)(k0 + row) * H + c4);
        }
        cp_commit();
    };

    load_tiles(0, 0);

    const int NIT = H / 32;
    for (int it = 0; it < NIT; it++) {
        if (it + 1 < NIT) {
            load_tiles((it + 1) & 1, (it + 1) * 32);
            cp_wait<1>();
        } else {
            cp_wait<0>();
        }
        __syncthreads();

        const uint32_t* as = (const uint32_t*)(sm + (it & 1) * STG);
        const uint32_t* bs = as + ASZ;

        #pragma unroll
        for (int kk = 0; kk < 4; kk++) {
            const int k = kk * 8;
            uint32_t a[2][4];
            #pragma unroll
            for (int mt = 0; mt < 2; mt++) {
                int m = mb + mt * 16 + g;
                a[mt][0] = as[(size_t)m * ASP + k + tg];
                a[mt][1] = as[(size_t)(m + 8) * ASP + k + tg];
                a[mt][2] = as[(size_t)m * ASP + k + tg + 4];
                a[mt][3] = as[(size_t)(m + 8) * ASP + k + tg + 4];
            }
            #pragma unroll
            for (int nt = 0; nt < 8; nt++) {
                int n = nb + nt * 8 + g;
                uint32_t b0 = bs[(size_t)(k + tg) * BSP + n];
                uint32_t b1 = bs[(size_t)(k + tg + 4) * BSP + n];
                #pragma unroll
                for (int mt = 0; mt < 2; mt++) {
                    asm volatile(
                        "mma.sync.aligned.m16n8k8.row.col.f32.tf32.tf32.f32 "
                        "{%0,%1,%2,%3}, {%4,%5,%6,%7}, {%8,%9}, {%0,%1,%2,%3};"
                        : "+f"(c[mt][nt][0]), "+f"(c[mt][nt][1]),
                          "+f"(c[mt][nt][2]), "+f"(c[mt][nt][3])
                        : "r"(a[mt][0]), "r"(a[mt][1]), "r"(a[mt][2]), "r"(a[mt][3]),
                          "r"(b0), "r"(b1));
                }
            }
        }
        __syncthreads();
    }

    if (inj_idx) {
        // inject epilogue: scatter rows into h_glob with dinv scaling
        #pragma unroll
        for (int mt = 0; mt < 2; mt++) {
            int r0 = mb + mt * 16 + g;
            int row0 = br * 128 + r0;
            int row1 = row0 + 8;
            int n0 = __ldg(&inj_idx[row0]);
            int n1 = __ldg(&inj_idx[row1]);
            float d0 = g_dinv_glob[n0];
            float d1 = g_dinv_glob[n1];
            float* p0 = g_h_glob + (size_t)n0 * H + bc * 128;
            float* p1 = g_h_glob + (size_t)n1 * H + bc * 128;
            #pragma unroll
            for (int nt = 0; nt < 8; nt++) {
                int col = nb + nt * 8 + 2 * tg;
                red_add_v2(p0 + col, c[mt][nt][0] * d0, c[mt][nt][1] * d0);
                red_add_v2(p1 + col, c[mt][nt][2] * d1, c[mt][nt][3] * d1);
            }
        }
        return;
    }

    float* Cb = C + (size_t)br * 128 * H + bc * 128;
    #pragma unroll
    for (int mt = 0; mt < 2; mt++) {
        int r0 = mb + mt * 16 + g;
        float s0 = 1.0f, s1 = 1.0f;
        if (rowscale) {
            s0 = __ldg(&rowscale[br * 128 + r0]);
            s1 = __ldg(&rowscale[br * 128 + r0 + 8]);
        }
        #pragma unroll
        for (int nt = 0; nt < 8; nt++) {
            int col = nb + nt * 8 + 2 * tg;
            *(float2*)(Cb + (size_t)r0 * H + col)       = make_float2(c[mt][nt][0] * s0, c[mt][nt][1] * s0);
            *(float2*)(Cb + (size_t)(r0 + 8) * H + col) = make_float2(c[mt][nt][2] * s1, c[mt][nt][3] * s1);
        }
    }
}

// ---------------------------------------------------------------------------
// counting sort (both graphs batched)
// ---------------------------------------------------------------------------
__global__ void k_blocksum_all(int NB_sub) {
    __shared__ int sh[256];
    int t = threadIdx.x;
    bool is_sub = (blockIdx.x < NB_sub);
    const int* cnt = is_sub ? g_cnt_sub : g_cnt_glob;
    int cb = is_sub ? blockIdx.x : blockIdx.x - NB_sub;
    sh[t] = cnt[cb * 256 + t];
    __syncthreads();
    #pragma unroll
    for (int s = 128; s > 0; s >>= 1) {
        if (t < s) sh[t] += sh[t + s];
        __syncthreads();
    }
    if (t == 0) (is_sub ? g_bsum_sub : g_bsum_glob)[cb] = sh[0];
}

__global__ void k_scan_bsum_all(int NB_sub, int NB_glob) {
    __shared__ int sh[256];
    int t = threadIdx.x;
    int* bsum = (blockIdx.x == 0) ? g_bsum_sub : g_bsum_glob;
    int NB = (blockIdx.x == 0) ? NB_sub : NB_glob;
    sh[t] = (t < NB) ? bsum[t] : 0;
    __syncthreads();
    #pragma unroll
    for (int d = 1; d < 256; d <<= 1) {
        int v = (t >= d) ? sh[t - d] : 0;
        __syncthreads();
        sh[t] += v;
        __syncthreads();
    }
    int ex = (t == 0) ? 0 : sh[t - 1];
    if (t < NB) bsum[t] = ex;
}

__global__ void k_scan_chunks_all(int NB_sub, int n_sub, int n_glob) {
    __shared__ int sh[256];
    int t = threadIdx.x;
    bool is_sub = (blockIdx.x < NB_sub);
    const int* cnt = is_sub ? g_cnt_sub : g_cnt_glob;
    const int* bsum = is_sub ? g_bsum_sub : g_bsum_glob;
    int* off = is_sub ? g_off_sub : g_off_glob;
    int* cur = is_sub ? g_cur_sub : g_cur_glob;
    int N = is_sub ? n_sub : n_glob;
    int cb = is_sub ? blockIdx.x : blockIdx.x - NB_sub;
    int i = cb * 256 + t;
    int c = cnt[i];
    sh[t] = c;
    __syncthreads();
    #pragma unroll
    for (int d = 1; d < 256; d <<= 1) {
        int v = (t >= d) ? sh[t - d] : 0;
        __syncthreads();
        sh[t] += v;
        __syncthreads();
    }
    int excl = sh[t] - c + bsum[cb];
    off[i] = excl;
    cur[i] = excl;
    if (i == N - 1) off[N] = excl + c;
}

__global__ void k_bucket_all(const int* __restrict__ rows_sub,
                             const int* __restrict__ cols_sub, int E_sub,
                             const int* __restrict__ rows_glob,
                             const int* __restrict__ cols_glob, int E_glob) {
    int i = blockIdx.x * blockDim.x + threadIdx.x;
    if (i < E_sub) {
        int c = cols_sub[i];
        int p = atomicAdd(&g_cur_sub[c], 1);
        g_srcs_sub[p] = rows_sub[i];
    }
    int e = i - E_sub;
    if (e >= 0 && e < E_glob) {
        int c = cols_glob[e];
        int p = atomicAdd(&g_cur_glob[c], 1);
        g_srcs_glob[p] = rows_glob[e];
    }
}

// ---------------------------------------------------------------------------
// sub gather: warp per node; lane owns float4 {lane, lane+32}; 4-edge batch.
// ---------------------------------------------------------------------------
__device__ __forceinline__ void f4_add2(float4 v0, float4 v1, float* acc) {
    acc[0] += v0.x; acc[1] += v0.y; acc[2] += v0.z; acc[3] += v0.w;
    acc[4] += v1.x; acc[5] += v1.y; acc[6] += v1.z; acc[7] += v1.w;
}

__global__ __launch_bounds__(256) void k_gather_sub(const float4* __restrict__ h,
                                                    const float* __restrict__ bias,
                                                    const int* __restrict__ batch, int N) {
    int warp = (blockIdx.x * blockDim.x + threadIdx.x) >> 5;
    int lane = threadIdx.x & 31;
    if (warp >= N) return;

    int base = g_off_sub[warp];
    int end  = g_off_sub[warp + 1];
    const int* srcs = g_srcs_sub;

    float acc[8];
    {
        float4 s0 = __ldg(h + (size_t)warp * 64 + lane);
        float4 s1 = __ldg(h + (size_t)warp * 64 + lane + 32);
        acc[0] = s0.x; acc[1] = s0.y; acc[2] = s0.z; acc[3] = s0.w;
        acc[4] = s1.x; acc[5] = s1.y; acc[6] = s1.z; acc[7] = s1.w;
    }
    int e = base;
    for (; e + 4 <= end; e += 4) {
        int r0 = __ldg(&srcs[e + 0]);
        int r1 = __ldg(&srcs[e + 1]);
        int r2 = __ldg(&srcs[e + 2]);
        int r3 = __ldg(&srcs[e + 3]);
        float4 a0 = __ldg(h + (size_t)r0 * 64 + lane);
        float4 b0 = __ldg(h + (size_t)r0 * 64 + lane + 32);
        float4 a1 = __ldg(h + (size_t)r1 * 64 + lane);
        float4 b1 = __ldg(h + (size_t)r1 * 64 + lane + 32);
        float4 a2 = __ldg(h + (size_t)r2 * 64 + lane);
        float4 b2 = __ldg(h + (size_t)r2 * 64 + lane + 32);
        float4 a3 = __ldg(h + (size_t)r3 * 64 + lane);
        float4 b3 = __ldg(h + (size_t)r3 * 64 + lane + 32);
        f4_add2(a0, b0, acc);
        f4_add2(a1, b1, acc);
        f4_add2(a2, b2, acc);
        f4_add2(a3, b3, acc);
    }
    for (; e < end; e++) {
        int r = __ldg(&srcs[e]);
        float4 a = __ldg(h + (size_t)r * 64 + lane);
        float4 b = __ldg(h + (size_t)r * 64 + lane + 32);
        f4_add2(a, b, acc);
    }

    float di = g_dinv_sub[warp];
    int s = batch[warp];
    float ic = 1.0f / fmaxf(g_pool_cnt[s], 1.0f);
    const float* bp = bias + 4 * lane;
    #pragma unroll
    for (int i = 0; i < 4; i++)
        acc[i] = fmaxf(acc[i] * di + __ldg(bp + i), 0.0f) * ic;
    #pragma unroll
    for (int i = 0; i < 4; i++)
        acc[4 + i] = fmaxf(acc[4 + i] * di + __ldg(bp + 128 + i), 0.0f) * ic;
    float* ps = g_pool_sum + (size_t)s * H;
    red_add_v4(ps + 4 * lane,       acc[0], acc[1], acc[2], acc[3]);
    red_add_v4(ps + 128 + 4 * lane, acc[4], acc[5], acc[6], acc[7]);
}

// ---------------------------------------------------------------------------
// glob gather: warp per (node, channel-half); 8-edge batch; fused final FC.
// ---------------------------------------------------------------------------
__global__ __launch_bounds__(512) void k_gather_glob(const float4* __restrict__ h,
                                                     const float* __restrict__ bias,
                                                     const float* __restrict__ fc_W,
                                                     const float* __restrict__ fc_b,
                                                     float* __restrict__ out,
                                                     int N, float inv_n) {
    __shared__ float sh[H];
    __shared__ float ge[H];
    __shared__ int s_last;
    int t = threadIdx.x;
    if (t < H) sh[t] = 0.0f;
    __syncthreads();

    int gwarp = (blockIdx.x * blockDim.x + t) >> 5;
    int lane = t & 31;
    int node = gwarp >> 1;
    int half = gwarp & 1;
    if (node < N) {
        int base = g_off_glob[node];
        int end  = g_off_glob[node + 1];
        const int* srcs = g_srcs_glob;
        int fo = half * 32 + lane;

        float4 acc = __ldg(h + (size_t)node * 64 + fo);

        int e = base;
        for (; e + 8 <= end; e += 8) {
            int r0 = __ldg(&srcs[e + 0]);
            int r1 = __ldg(&srcs[e + 1]);
            int r2 = __ldg(&srcs[e + 2]);
            int r3 = __ldg(&srcs[e + 3]);
            int r4 = __ldg(&srcs[e + 4]);
            int r5 = __ldg(&srcs[e + 5]);
            int r6 = __ldg(&srcs[e + 6]);
            int r7 = __ldg(&srcs[e + 7]);
            float4 v0 = __ldg(h + (size_t)r0 * 64 + fo);
            float4 v1 = __ldg(h + (size_t)r1 * 64 + fo);
            float4 v2 = __ldg(h + (size_t)r2 * 64 + fo);
            float4 v3 = __ldg(h + (size_t)r3 * 64 + fo);
            float4 v4 = __ldg(h + (size_t)r4 * 64 + fo);
            float4 v5 = __ldg(h + (size_t)r5 * 64 + fo);
            float4 v6 = __ldg(h + (size_t)r6 * 64 + fo);
            float4 v7 = __ldg(h + (size_t)r7 * 64 + fo);
            acc.x += v0.x + v1.x + v2.x + v3.x + v4.x + v5.x + v6.x + v7.x;
            acc.y += v0.y + v1.y + v2.y + v3.y + v4.y + v5.y + v6.y + v7.y;
            acc.z += v0.z + v1.z + v2.z + v3.z + v4.z + v5.z + v6.z + v7.z;
            acc.w += v0.w + v1.w + v2.w + v3.w + v4.w + v5.w + v6.w + v7.w;
        }
        for (; e < end; e++) {
            int r = __ldg(&srcs[e]);
            float4 v = __ldg(h + (size_t)r * 64 + fo);
            acc.x += v.x; acc.y += v.y; acc.z += v.z; acc.w += v.w;
        }

        float di = g_dinv_glob[node];
        int ch = 4 * fo;
        const float* bp = bias + ch;
        atomicAdd(&sh[ch + 0], fmaxf(acc.x * di + __ldg(bp + 0), 0.0f));
        atomicAdd(&sh[ch + 1], fmaxf(acc.y * di + __ldg(bp + 1), 0.0f));
        atomicAdd(&sh[ch + 2], fmaxf(acc.z * di + __ldg(bp + 2), 0.0f));
        atomicAdd(&sh[ch + 3], fmaxf(acc.w * di + __ldg(bp + 3), 0.0f));
    }
    __syncthreads();
    if (t < H) atomicAdd(&g_gemb[t], sh[t]);

    // last-block fused FC
    if (t == 0) {
        __threadfence();
        int p = atomicAdd(&g_done, 1);
        s_last = (p == (int)gridDim.x - 1) ? 1 : 0;
    }
    __syncthreads();
    if (s_last) {
        if (t < H) ge[t] = __ldcg(&g_gemb[t]) * inv_n;
        __syncthreads();
        if (t < H) {
            float s = 0.0f;
            #pragma unroll 8
            for (int f = 0; f < H; f++) s += ge[f] * fc_W[t * H + f];
            out[t] = s + fc_b[t];
        }
    }
}

// ---------------------------------------------------------------------------
extern "C" void kernel_launch(void* const* d_in, const int* in_sizes, int n_in,
                              void* d_out, int out_size) {
    const float* x_sub      = (const float*)d_in[0];
    const int*   ei_sub     = (const int*)  d_in[1];
    const int*   batch_sub  = (const int*)  d_in[2];
    const int*   sub_index  = (const int*)  d_in[3];
    const float* x_glob     = (const float*)d_in[4];
    const int*   ei_glob    = (const int*)  d_in[5];
    const float* W_sub      = (const float*)d_in[7];
    const float* b_sub      = (const float*)d_in[8];
    const float* W_glob     = (const float*)d_in[9];
    const float* b_glob     = (const float*)d_in[10];
    const float* fc_W       = (const float*)d_in[11];
    const float* fc_b       = (const float*)d_in[12];
    float* out = (float*)d_out;

    const int n_sub  = in_sizes[0] / H;
    const int E_sub  = in_sizes[1] / 2;
    const int S      = in_sizes[3];
    const int n_glob = in_sizes[4] / H;
    const int E_glob = in_sizes[5] / 2;

    const int* rows_sub  = ei_sub;
    const int* cols_sub  = ei_sub + E_sub;
    const int* rows_glob = ei_glob;
    const int* cols_glob = ei_glob + E_glob;

    float* h_sub   ; cudaGetSymbolAddress((void**)&h_sub,    g_h_sub);
    float* h_glob  ; cudaGetSymbolAddress((void**)&h_glob,   g_h_glob);
    float* psum    ; cudaGetSymbolAddress((void**)&psum,     g_pool_sum);
    float* dinv_sub ; cudaGetSymbolAddress((void**)&dinv_sub,  g_dinv_sub);
    float* dinv_glob; cudaGetSymbolAddress((void**)&dinv_glob, g_dinv_glob);

    cudaFuncSetAttribute(k_mma, cudaFuncAttributeMaxDynamicSharedMemorySize, MMA_SMEM);

    static cudaStream_t s_sort = nullptr, s_glob = nullptr;
    static cudaEvent_t evRoot = nullptr, evSort = nullptr, evGlobM = nullptr;
    if (!s_sort) {
        cudaStreamCreateWithFlags(&s_sort, cudaStreamNonBlocking);
        cudaStreamCreateWithFlags(&s_glob, cudaStreamNonBlocking);
        cudaEventCreateWithFlags(&evRoot,  cudaEventDisableTiming);
        cudaEventCreateWithFlags(&evSort,  cudaEventDisableTiming);
        cudaEventCreateWithFlags(&evGlobM, cudaEventDisableTiming);
    }

    const int T = 256;
    const int NB_sub  = n_sub  / 256;
    const int NB_glob = n_glob / 256;

    // ---- serial prologue on capture stream ----
    {
        int span = S * H;
        if (n_glob > span) span = n_glob;
        k_init<<<(span + T - 1) / T, T>>>(n_sub, n_glob, S);
    }
    k_count_all<<<(E_glob + T - 1) / T, T>>>(cols_sub, E_sub, cols_glob, E_glob,
                                             batch_sub, n_sub);
    k_dinv<<<(n_glob + T - 1) / T, T>>>(n_sub, n_glob);
    cudaEventRecord(evRoot, 0);

    // ---- branch A (s_sort): counting sort ----
    cudaStreamWaitEvent(s_sort, evRoot, 0);
    k_blocksum_all<<<NB_sub + NB_glob, 256, 0, s_sort>>>(NB_sub);
    k_scan_bsum_all<<<2, 256, 0, s_sort>>>(NB_sub, NB_glob);
    k_scan_chunks_all<<<NB_sub + NB_glob, 256, 0, s_sort>>>(NB_sub, n_sub, n_glob);
    k_bucket_all<<<(E_sub + E_glob + T - 1) / T, T, 0, s_sort>>>(rows_sub, cols_sub, E_sub,
                                                                 rows_glob, cols_glob, E_glob);
    cudaEventRecord(evSort, s_sort);

    // ---- branch B (s_glob): big glob GEMM ----
    cudaStreamWaitEvent(s_glob, evRoot, 0);
    k_mma<<<dim3(2, n_glob / 128), 256, MMA_SMEM, s_glob>>>(x_glob, W_glob, h_glob,
                                                            dinv_glob, (const int*)nullptr,
                                                            n_glob);
    cudaEventRecord(evGlobM, s_glob);

    // ---- main stream: sub pipeline ----
    k_mma<<<dim3(2, n_sub / 128), 256, MMA_SMEM>>>(x_sub, W_sub, h_sub, dinv_sub,
                                                   (const int*)nullptr, n_sub);
    cudaStreamWaitEvent(0, evSort, 0);
    k_gather_sub<<<(n_sub * 32 + 255) / 256, 256>>>((const float4*)h_sub, b_sub,
                                                    batch_sub, n_sub);
    // ---- join: pool GEMM injects straight into h_glob (needs mma_glob done) ----
    cudaStreamWaitEvent(0, evGlobM, 0);
    k_mma<<<dim3(2, S / 128), 256, MMA_SMEM>>>(psum, W_glob, (float*)nullptr,
                                               (const float*)nullptr, sub_index, S);
    // ---- glob gather (+fused FC) ----
    k_gather_glob<<<(n_glob * 64 + 511) / 512, 512>>>((const float4*)h_glob, b_glob,
                                                      fc_W, fc_b, out, n_glob,
                                                      1.0f / (float)n_glob);
}

// round 14
// speedup vs baseline: 1.2882x; 1.0646x over previous
#include <cuda_runtime.h>
#include <cuda_bf16.h>
#include <cstdint>

// ---------------------------------------------------------------------------
// GCNWithSubgraphs: gather-based, 2-stage cp.async tf32 MMA GEMMs
// (dinv-prescaled fp32 output), pure-sum gathers, stream-forked graph.
// gemb reduction spread over 64 line-distinct replicas (L2 atomic fix).
// ---------------------------------------------------------------------------

#define H 256
#define MAX_NSUB  32768
#define MAX_NGLOB 65536
#define MAX_S     1024
#define MAX_ESUB  262144
#define MAX_EGLOB 1048576
#define NREP 64

__device__ float g_h_sub[MAX_NSUB * H];
__device__ float g_h_glob[MAX_NGLOB * H];
__device__ float g_pooledW[MAX_S * H];
__device__ float g_pool_sum[MAX_S * H];
__device__ float g_pool_cnt[MAX_S];
__device__ float g_gpart[NREP * H];   // 64 replicas of gemb partials

__device__ int   g_cnt_sub[MAX_NSUB];
__device__ int   g_off_sub[MAX_NSUB + 1];
__device__ int   g_cur_sub[MAX_NSUB];
__device__ float g_dinv_sub[MAX_NSUB];
__device__ int   g_srcs_sub[MAX_ESUB];

__device__ int   g_cnt_glob[MAX_NGLOB];
__device__ int   g_off_glob[MAX_NGLOB + 1];
__device__ int   g_cur_glob[MAX_NGLOB];
__device__ float g_dinv_glob[MAX_NGLOB];
__device__ int   g_srcs_glob[MAX_EGLOB];

__device__ int   g_bsum_sub[256];
__device__ int   g_bsum_glob[256];

__device__ __forceinline__ void red_add_v4(float* a, float v0, float v1, float v2, float v3) {
    asm volatile("red.global.add.v4.f32 [%0], {%1,%2,%3,%4};"
                 :: "l"(a), "f"(v0), "f"(v1), "f"(v2), "f"(v3)
                 : "memory");
}

__device__ __forceinline__ void cp_async16(void* smem_dst, const void* gmem_src) {
    uint32_t s = (uint32_t)__cvta_generic_to_shared(smem_dst);
    asm volatile("cp.async.cg.shared.global [%0], [%1], 16;" :: "r"(s), "l"(gmem_src));
}
__device__ __forceinline__ void cp_commit() {
    asm volatile("cp.async.commit_group;" ::: "memory");
}
template <int N>
__device__ __forceinline__ void cp_wait() {
    asm volatile("cp.async.wait_group %0;" :: "n"(N) : "memory");
}

// ---------------------------------------------------------------------------
__global__ void k_init(int n_sub, int n_glob, int s) {
    int i = blockIdx.x * blockDim.x + threadIdx.x;
    if (i < n_sub)  g_cnt_sub[i]  = 0;
    if (i < n_glob) g_cnt_glob[i] = 0;
    if (i < s * H)  g_pool_sum[i] = 0.0f;
    if (i < s)      g_pool_cnt[i] = 0.0f;
    if (i < NREP * H) g_gpart[i]  = 0.0f;
}

__global__ void k_count_all(const int* __restrict__ cols_sub, int E_sub,
                            const int* __restrict__ cols_glob, int E_glob,
                            const int* __restrict__ batch, int n_sub) {
    int i = blockIdx.x * blockDim.x + threadIdx.x;
    if (i < E_glob) atomicAdd(&g_cnt_glob[cols_glob[i]], 1);
    if (i < E_sub)  atomicAdd(&g_cnt_sub[cols_sub[i]], 1);
    if (i < n_sub)  atomicAdd(&g_pool_cnt[batch[i]], 1.0f);
}

__global__ void k_dinv(int n_sub, int n_glob) {
    int i = blockIdx.x * blockDim.x + threadIdx.x;
    if (i < n_sub)  g_dinv_sub[i]  = rsqrtf((float)(g_cnt_sub[i] + 1));
    if (i < n_glob) g_dinv_glob[i] = rsqrtf((float)(g_cnt_glob[i] + 1));
}

// ---------------------------------------------------------------------------
// tf32 MMA GEMM: C[M,256](f32) = (A[M,256] @ B[256,256]) * rowscale
// 2-stage cp.async, no STS, no cvt. 128x128 block, 256 thr, BK=32.
// ---------------------------------------------------------------------------
#define ASP 36
#define BSP 136
#define ASZ (128 * ASP)
#define BSZ (32 * BSP)
#define STG (ASZ + BSZ)
#define MMA_SMEM (2 * STG * 4)

__global__ __launch_bounds__(256) void k_mma(const float* __restrict__ A,
                                             const float* __restrict__ B,
                                             float* __restrict__ C,
                                             const float* __restrict__ rowscale, int M) {
    extern __shared__ float sm[];

    const int tid  = threadIdx.x;
    const int lane = tid & 31;
    const int wid  = tid >> 5;
    const int warpM = wid >> 1;
    const int warpN = wid & 1;
    const int g  = lane >> 2;
    const int tg = lane & 3;
    const int mb = warpM * 32;
    const int nb = warpN * 64;

    const int bc = blockIdx.x;
    const int br = blockIdx.y;

    const float* Ab = A + (size_t)br * 128 * H;
    const float* Bb = B + bc * 128;

    float c[2][8][4];
    #pragma unroll
    for (int mt = 0; mt < 2; mt++)
        #pragma unroll
        for (int nt = 0; nt < 8; nt++)
            #pragma unroll
            for (int i = 0; i < 4; i++) c[mt][nt][i] = 0.0f;

    auto load_tiles = [&](int stage, int k0) {
        float* as = sm + stage * STG;
        float* bs = as + ASZ;
        #pragma unroll
        for (int p = 0; p < 4; p++) {
            int idx = tid + p * 256;
            int row = idx >> 3;
            int c4  = (idx & 7) * 4;
            cp_async16(&as[row * ASP + c4], Ab + (size_t)row * H + k0 + c4);
        }
        #pragma unroll
        for (int p = 0; p < 4; p++) {
            int idx = tid + p * 256;
            int row = idx >> 5;
            int c4  = (idx & 31) * 4;
            cp_async16(&bs[row * BSP + c4], Bb + (size_t)(k0 + row) * H + c4);
        }
        cp_commit();
    };

    load_tiles(0, 0);

    const int NIT = H / 32;
    for (int it = 0; it < NIT; it++) {
        if (it + 1 < NIT) {
            load_tiles((it + 1) & 1, (it + 1) * 32);
            cp_wait<1>();
        } else {
            cp_wait<0>();
        }
        __syncthreads();

        const uint32_t* as = (const uint32_t*)(sm + (it & 1) * STG);
        const uint32_t* bs = as + ASZ;

        #pragma unroll
        for (int kk = 0; kk < 4; kk++) {
            const int k = kk * 8;
            uint32_t a[2][4];
            #pragma unroll
            for (int mt = 0; mt < 2; mt++) {
                int m = mb + mt * 16 + g;
                a[mt][0] = as[(size_t)m * ASP + k + tg];
                a[mt][1] = as[(size_t)(m + 8) * ASP + k + tg];
                a[mt][2] = as[(size_t)m * ASP + k + tg + 4];
                a[mt][3] = as[(size_t)(m + 8) * ASP + k + tg + 4];
            }
            #pragma unroll
            for (int nt = 0; nt < 8; nt++) {
                int n = nb + nt * 8 + g;
                uint32_t b0 = bs[(size_t)(k + tg) * BSP + n];
                uint32_t b1 = bs[(size_t)(k + tg + 4) * BSP + n];
                #pragma unroll
                for (int mt = 0; mt < 2; mt++) {
                    asm volatile(
                        "mma.sync.aligned.m16n8k8.row.col.f32.tf32.tf32.f32 "
                        "{%0,%1,%2,%3}, {%4,%5,%6,%7}, {%8,%9}, {%0,%1,%2,%3};"
                        : "+f"(c[mt][nt][0]), "+f"(c[mt][nt][1]),
                          "+f"(c[mt][nt][2]), "+f"(c[mt][nt][3])
                        : "r"(a[mt][0]), "r"(a[mt][1]), "r"(a[mt][2]), "r"(a[mt][3]),
                          "r"(b0), "r"(b1));
                }
            }
        }
        __syncthreads();
    }

    float* Cb = C + (size_t)br * 128 * H + bc * 128;
    #pragma unroll
    for (int mt = 0; mt < 2; mt++) {
        int r0 = mb + mt * 16 + g;
        float s0 = 1.0f, s1 = 1.0f;
        if (rowscale) {
            s0 = __ldg(&rowscale[br * 128 + r0]);
            s1 = __ldg(&rowscale[br * 128 + r0 + 8]);
        }
        #pragma unroll
        for (int nt = 0; nt < 8; nt++) {
            int col = nb + nt * 8 + 2 * tg;
            *(float2*)(Cb + (size_t)r0 * H + col)       = make_float2(c[mt][nt][0] * s0, c[mt][nt][1] * s0);
            *(float2*)(Cb + (size_t)(r0 + 8) * H + col) = make_float2(c[mt][nt][2] * s1, c[mt][nt][3] * s1);
        }
    }
}

// ---------------------------------------------------------------------------
// counting sort (both graphs batched)
// ---------------------------------------------------------------------------
__global__ void k_blocksum_all(int NB_sub) {
    __shared__ int sh[256];
    int t = threadIdx.x;
    bool is_sub = (blockIdx.x < NB_sub);
    const int* cnt = is_sub ? g_cnt_sub : g_cnt_glob;
    int cb = is_sub ? blockIdx.x : blockIdx.x - NB_sub;
    sh[t] = cnt[cb * 256 + t];
    __syncthreads();
    #pragma unroll
    for (int s = 128; s > 0; s >>= 1) {
        if (t < s) sh[t] += sh[t + s];
        __syncthreads();
    }
    if (t == 0) (is_sub ? g_bsum_sub : g_bsum_glob)[cb] = sh[0];
}

__global__ void k_scan_bsum_all(int NB_sub, int NB_glob) {
    __shared__ int sh[256];
    int t = threadIdx.x;
    int* bsum = (blockIdx.x == 0) ? g_bsum_sub : g_bsum_glob;
    int NB = (blockIdx.x == 0) ? NB_sub : NB_glob;
    sh[t] = (t < NB) ? bsum[t] : 0;
    __syncthreads();
    #pragma unroll
    for (int d = 1; d < 256; d <<= 1) {
        int v = (t >= d) ? sh[t - d] : 0;
        __syncthreads();
        sh[t] += v;
        __syncthreads();
    }
    int ex = (t == 0) ? 0 : sh[t - 1];
    if (t < NB) bsum[t] = ex;
}

__global__ void k_scan_chunks_all(int NB_sub, int n_sub, int n_glob) {
    __shared__ int sh[256];
    int t = threadIdx.x;
    bool is_sub = (blockIdx.x < NB_sub);
    const int* cnt = is_sub ? g_cnt_sub : g_cnt_glob;
    const int* bsum = is_sub ? g_bsum_sub : g_bsum_glob;
    int* off = is_sub ? g_off_sub : g_off_glob;
    int* cur = is_sub ? g_cur_sub : g_cur_glob;
    int N = is_sub ? n_sub : n_glob;
    int cb = is_sub ? blockIdx.x : blockIdx.x - NB_sub;
    int i = cb * 256 + t;
    int c = cnt[i];
    sh[t] = c;
    __syncthreads();
    #pragma unroll
    for (int d = 1; d < 256; d <<= 1) {
        int v = (t >= d) ? sh[t - d] : 0;
        __syncthreads();
        sh[t] += v;
        __syncthreads();
    }
    int excl = sh[t] - c + bsum[cb];
    off[i] = excl;
    cur[i] = excl;
    if (i == N - 1) off[N] = excl + c;
}

__global__ void k_bucket_all(const int* __restrict__ rows_sub,
                             const int* __restrict__ cols_sub, int E_sub,
                             const int* __restrict__ rows_glob,
                             const int* __restrict__ cols_glob, int E_glob) {
    int i = blockIdx.x * blockDim.x + threadIdx.x;
    if (i < E_sub) {
        int c = cols_sub[i];
        int p = atomicAdd(&g_cur_sub[c], 1);
        g_srcs_sub[p] = rows_sub[i];
    }
    int e = i - E_sub;
    if (e >= 0 && e < E_glob) {
        int c = cols_glob[e];
        int p = atomicAdd(&g_cur_glob[c], 1);
        g_srcs_glob[p] = rows_glob[e];
    }
}

// ---------------------------------------------------------------------------
// sub gather: warp per node; lane owns float4 {lane, lane+32}; 4-edge batch.
// ---------------------------------------------------------------------------
__device__ __forceinline__ void f4_add2(float4 v0, float4 v1, float* acc) {
    acc[0] += v0.x; acc[1] += v0.y; acc[2] += v0.z; acc[3] += v0.w;
    acc[4] += v1.x; acc[5] += v1.y; acc[6] += v1.z; acc[7] += v1.w;
}

__global__ __launch_bounds__(256) void k_gather_sub(const float4* __restrict__ h,
                                                    const float* __restrict__ bias,
                                                    const int* __restrict__ batch, int N) {
    int warp = (blockIdx.x * blockDim.x + threadIdx.x) >> 5;
    int lane = threadIdx.x & 31;
    if (warp >= N) return;

    int base = g_off_sub[warp];
    int end  = g_off_sub[warp + 1];
    const int* srcs = g_srcs_sub;

    float acc[8];
    {
        float4 s0 = __ldg(h + (size_t)warp * 64 + lane);
        float4 s1 = __ldg(h + (size_t)warp * 64 + lane + 32);
        acc[0] = s0.x; acc[1] = s0.y; acc[2] = s0.z; acc[3] = s0.w;
        acc[4] = s1.x; acc[5] = s1.y; acc[6] = s1.z; acc[7] = s1.w;
    }
    int e = base;
    for (; e + 4 <= end; e += 4) {
        int r0 = __ldg(&srcs[e + 0]);
        int r1 = __ldg(&srcs[e + 1]);
        int r2 = __ldg(&srcs[e + 2]);
        int r3 = __ldg(&srcs[e + 3]);
        float4 a0 = __ldg(h + (size_t)r0 * 64 + lane);
        float4 b0 = __ldg(h + (size_t)r0 * 64 + lane + 32);
        float4 a1 = __ldg(h + (size_t)r1 * 64 + lane);
        float4 b1 = __ldg(h + (size_t)r1 * 64 + lane + 32);
        float4 a2 = __ldg(h + (size_t)r2 * 64 + lane);
        float4 b2 = __ldg(h + (size_t)r2 * 64 + lane + 32);
        float4 a3 = __ldg(h + (size_t)r3 * 64 + lane);
        float4 b3 = __ldg(h + (size_t)r3 * 64 + lane + 32);
        f4_add2(a0, b0, acc);
        f4_add2(a1, b1, acc);
        f4_add2(a2, b2, acc);
        f4_add2(a3, b3, acc);
    }
    for (; e < end; e++) {
        int r = __ldg(&srcs[e]);
        float4 a = __ldg(h + (size_t)r * 64 + lane);
        float4 b = __ldg(h + (size_t)r * 64 + lane + 32);
        f4_add2(a, b, acc);
    }

    float di = g_dinv_sub[warp];
    int s = batch[warp];
    float ic = 1.0f / fmaxf(g_pool_cnt[s], 1.0f);
    const float* bp = bias + 4 * lane;
    #pragma unroll
    for (int i = 0; i < 4; i++)
        acc[i] = fmaxf(acc[i] * di + __ldg(bp + i), 0.0f) * ic;
    #pragma unroll
    for (int i = 0; i < 4; i++)
        acc[4 + i] = fmaxf(acc[4 + i] * di + __ldg(bp + 128 + i), 0.0f) * ic;
    float* ps = g_pool_sum + (size_t)s * H;
    red_add_v4(ps + 4 * lane,       acc[0], acc[1], acc[2], acc[3]);
    red_add_v4(ps + 128 + 4 * lane, acc[4], acc[5], acc[6], acc[7]);
}

// ---------------------------------------------------------------------------
// glob gather: warp per (node, channel-half); 8-edge batch.
// Block partial -> g_gpart[blockIdx & 63] (64 line-distinct replicas).
// ---------------------------------------------------------------------------
__global__ __launch_bounds__(512) void k_gather_glob(const float4* __restrict__ h,
                                                     const float* __restrict__ bias, int N) {
    __shared__ float sh[H];
    int t = threadIdx.x;
    if (t < H) sh[t] = 0.0f;
    __syncthreads();

    int gwarp = (blockIdx.x * blockDim.x + t) >> 5;
    int lane = t & 31;
    int node = gwarp >> 1;
    int half = gwarp & 1;
    if (node < N) {
        int base = g_off_glob[node];
        int end  = g_off_glob[node + 1];
        const int* srcs = g_srcs_glob;
        int fo = half * 32 + lane;

        float4 acc = __ldg(h + (size_t)node * 64 + fo);

        int e = base;
        for (; e + 8 <= end; e += 8) {
            int r0 = __ldg(&srcs[e + 0]);
            int r1 = __ldg(&srcs[e + 1]);
            int r2 = __ldg(&srcs[e + 2]);
            int r3 = __ldg(&srcs[e + 3]);
            int r4 = __ldg(&srcs[e + 4]);
            int r5 = __ldg(&srcs[e + 5]);
            int r6 = __ldg(&srcs[e + 6]);
            int r7 = __ldg(&srcs[e + 7]);
            float4 v0 = __ldg(h + (size_t)r0 * 64 + fo);
            float4 v1 = __ldg(h + (size_t)r1 * 64 + fo);
            float4 v2 = __ldg(h + (size_t)r2 * 64 + fo);
            float4 v3 = __ldg(h + (size_t)r3 * 64 + fo);
            float4 v4 = __ldg(h + (size_t)r4 * 64 + fo);
            float4 v5 = __ldg(h + (size_t)r5 * 64 + fo);
            float4 v6 = __ldg(h + (size_t)r6 * 64 + fo);
            float4 v7 = __ldg(h + (size_t)r7 * 64 + fo);
            acc.x += v0.x + v1.x + v2.x + v3.x + v4.x + v5.x + v6.x + v7.x;
            acc.y += v0.y + v1.y + v2.y + v3.y + v4.y + v5.y + v6.y + v7.y;
            acc.z += v0.z + v1.z + v2.z + v3.z + v4.z + v5.z + v6.z + v7.z;
            acc.w += v0.w + v1.w + v2.w + v3.w + v4.w + v5.w + v6.w + v7.w;
        }
        for (; e < end; e++) {
            int r = __ldg(&srcs[e]);
            float4 v = __ldg(h + (size_t)r * 64 + fo);
            acc.x += v.x; acc.y += v.y; acc.z += v.z; acc.w += v.w;
        }

        float di = g_dinv_glob[node];
        int ch = 4 * fo;
        const float* bp = bias + ch;
        atomicAdd(&sh[ch + 0], fmaxf(acc.x * di + __ldg(bp + 0), 0.0f));
        atomicAdd(&sh[ch + 1], fmaxf(acc.y * di + __ldg(bp + 1), 0.0f));
        atomicAdd(&sh[ch + 2], fmaxf(acc.z * di + __ldg(bp + 2), 0.0f));
        atomicAdd(&sh[ch + 3], fmaxf(acc.w * di + __ldg(bp + 3), 0.0f));
    }
    __syncthreads();
    if (t < H)
        atomicAdd(&g_gpart[((blockIdx.x & (NREP - 1)) << 8) + t], sh[t]);
}

// hs_glob[sub_index[g]] += pooledW[g] * dinv_glob[node]
__global__ void k_inject(const int* __restrict__ sub_index, int s) {
    int i = blockIdx.x * blockDim.x + threadIdx.x;
    if (i < s * 64) {
        int g  = i >> 6;
        int f4 = i & 63;
        int node = sub_index[g];
        float di = g_dinv_glob[node];
        float4 v = ((const float4*)g_pooledW)[i];
        red_add_v4(&g_h_glob[(size_t)node * H + 4 * f4],
                   v.x * di, v.y * di, v.z * di, v.w * di);
    }
}

// out[j] = (sum_r gpart[r]/n_glob) . fc_W[j,:] + fc_b[j]
__global__ void k_final(const float* __restrict__ fc_W, const float* __restrict__ fc_b,
                        float* __restrict__ out, float inv_n) {
    __shared__ float ge[H];
    int t = threadIdx.x;
    float s = 0.0f;
    #pragma unroll
    for (int r = 0; r < NREP; r++) s += g_gpart[r * H + t];
    ge[t] = s * inv_n;
    __syncthreads();
    float acc = 0.0f;
    #pragma unroll 8
    for (int f = 0; f < H; f++) acc += ge[f] * fc_W[t * H + f];
    out[t] = acc + fc_b[t];
}

// ---------------------------------------------------------------------------
extern "C" void kernel_launch(void* const* d_in, const int* in_sizes, int n_in,
                              void* d_out, int out_size) {
    const float* x_sub      = (const float*)d_in[0];
    const int*   ei_sub     = (const int*)  d_in[1];
    const int*   batch_sub  = (const int*)  d_in[2];
    const int*   sub_index  = (const int*)  d_in[3];
    const float* x_glob     = (const float*)d_in[4];
    const int*   ei_glob    = (const int*)  d_in[5];
    const float* W_sub      = (const float*)d_in[7];
    const float* b_sub      = (const float*)d_in[8];
    const float* W_glob     = (const float*)d_in[9];
    const float* b_glob     = (const float*)d_in[10];
    const float* fc_W       = (const float*)d_in[11];
    const float* fc_b       = (const float*)d_in[12];
    float* out = (float*)d_out;

    const int n_sub  = in_sizes[0] / H;
    const int E_sub  = in_sizes[1] / 2;
    const int S      = in_sizes[3];
    const int n_glob = in_sizes[4] / H;
    const int E_glob = in_sizes[5] / 2;

    const int* rows_sub  = ei_sub;
    const int* cols_sub  = ei_sub + E_sub;
    const int* rows_glob = ei_glob;
    const int* cols_glob = ei_glob + E_glob;

    float* h_sub   ; cudaGetSymbolAddress((void**)&h_sub,    g_h_sub);
    float* h_glob  ; cudaGetSymbolAddress((void**)&h_glob,   g_h_glob);
    float* pooledW ; cudaGetSymbolAddress((void**)&pooledW,  g_pooledW);
    float* psum    ; cudaGetSymbolAddress((void**)&psum,     g_pool_sum);
    float* dinv_sub ; cudaGetSymbolAddress((void**)&dinv_sub,  g_dinv_sub);
    float* dinv_glob; cudaGetSymbolAddress((void**)&dinv_glob, g_dinv_glob);

    cudaFuncSetAttribute(k_mma, cudaFuncAttributeMaxDynamicSharedMemorySize, MMA_SMEM);

    static cudaStream_t s_sort = nullptr, s_glob = nullptr;
    static cudaEvent_t evRoot = nullptr, evSort = nullptr, evGlobM = nullptr;
    if (!s_sort) {
        cudaStreamCreateWithFlags(&s_sort, cudaStreamNonBlocking);
        cudaStreamCreateWithFlags(&s_glob, cudaStreamNonBlocking);
        cudaEventCreateWithFlags(&evRoot,  cudaEventDisableTiming);
        cudaEventCreateWithFlags(&evSort,  cudaEventDisableTiming);
        cudaEventCreateWithFlags(&evGlobM, cudaEventDisableTiming);
    }

    const int T = 256;
    const int NB_sub  = n_sub  / 256;
    const int NB_glob = n_glob / 256;

    // ---- serial prologue on capture stream ----
    {
        int span = S * H;
        if (n_glob > span) span = n_glob;
        k_init<<<(span + T - 1) / T, T>>>(n_sub, n_glob, S);
    }
    k_count_all<<<(E_glob + T - 1) / T, T>>>(cols_sub, E_sub, cols_glob, E_glob,
                                             batch_sub, n_sub);
    k_dinv<<<(n_glob + T - 1) / T, T>>>(n_sub, n_glob);
    cudaEventRecord(evRoot, 0);

    // ---- branch A (s_sort): counting sort ----
    cudaStreamWaitEvent(s_sort, evRoot, 0);
    k_blocksum_all<<<NB_sub + NB_glob, 256, 0, s_sort>>>(NB_sub);
    k_scan_bsum_all<<<2, 256, 0, s_sort>>>(NB_sub, NB_glob);
    k_scan_chunks_all<<<NB_sub + NB_glob, 256, 0, s_sort>>>(NB_sub, n_sub, n_glob);
    k_bucket_all<<<(E_sub + E_glob + T - 1) / T, T, 0, s_sort>>>(rows_sub, cols_sub, E_sub,
                                                                 rows_glob, cols_glob, E_glob);
    cudaEventRecord(evSort, s_sort);

    // ---- branch B (s_glob): big glob GEMM ----
    cudaStreamWaitEvent(s_glob, evRoot, 0);
    k_mma<<<dim3(2, n_glob / 128), 256, MMA_SMEM, s_glob>>>(x_glob, W_glob, h_glob,
                                                            dinv_glob, n_glob);
    cudaEventRecord(evGlobM, s_glob);

    // ---- main stream: sub pipeline ----
    k_mma<<<dim3(2, n_sub / 128), 256, MMA_SMEM>>>(x_sub, W_sub, h_sub, dinv_sub, n_sub);
    cudaStreamWaitEvent(0, evSort, 0);
    k_gather_sub<<<(n_sub * 32 + 255) / 256, 256>>>((const float4*)h_sub, b_sub,
                                                    batch_sub, n_sub);
    k_mma<<<dim3(2, S / 128), 256, MMA_SMEM>>>(psum, W_glob, pooledW,
                                               (const float*)nullptr, S);
    // ---- join + epilogue ----
    cudaStreamWaitEvent(0, evGlobM, 0);
    k_inject<<<(S * 64 + T - 1) / T, T>>>(sub_index, S);
    k_gather_glob<<<(n_glob * 64 + 511) / 512, 512>>>((const float4*)h_glob, b_glob, n_glob);
    k_final<<<1, H>>>(fc_W, fc_b, out, 1.0f / (float)n_glob);
}